// round 13
// baseline (speedup 1.0000x reference)
#include <cuda_runtime.h>
#include <cuda_bf16.h>
#include <cuda_fp16.h>
#include <math.h>
#include <stdint.h>

#define BB 4
#define SS 2048
#define DD 1024
#define NH 16
#define HDIM 64
#define MROWS (BB*SS)   /* 8192 */

#define SC_SCALE 0.180336880f   /* 0.125 * log2(e), folded into Q projection */

// ---------------- scratch (__device__ globals; allocs forbidden) ------------
__device__ __half g_xh[MROWS*DD];
__device__ __half g_qh[MROWS*DD];
__device__ __half g_kh[MROWS*DD];
__device__ __half g_vh[MROWS*DD];
__device__ __half g_ch[MROWS*DD];
__device__ __half g_wh[4][DD*DD];   // transposed fp16: [Wq, Wk, Wv, Wo]

// ---------------- ptx helpers -------------------------------------------------
static __device__ __forceinline__ void mma_f16(float* c, const uint32_t* a,
                                               const uint32_t* b) {
    asm volatile(
        "mma.sync.aligned.m16n8k16.row.col.f32.f16.f16.f32 "
        "{%0,%1,%2,%3}, {%4,%5,%6,%7}, {%8,%9}, {%0,%1,%2,%3};"
        : "+f"(c[0]), "+f"(c[1]), "+f"(c[2]), "+f"(c[3])
        : "r"(a[0]), "r"(a[1]), "r"(a[2]), "r"(a[3]), "r"(b[0]), "r"(b[1]));
}
static __device__ __forceinline__ void ldsm4(uint32_t* r, uint32_t a) {
    asm volatile("ldmatrix.sync.aligned.m8n8.x4.shared.b16 {%0,%1,%2,%3}, [%4];"
                 : "=r"(r[0]), "=r"(r[1]), "=r"(r[2]), "=r"(r[3]) : "r"(a));
}
static __device__ __forceinline__ void ldsm4t(uint32_t* r, uint32_t a) {
    asm volatile("ldmatrix.sync.aligned.m8n8.x4.trans.shared.b16 {%0,%1,%2,%3}, [%4];"
                 : "=r"(r[0]), "=r"(r[1]), "=r"(r[2]), "=r"(r[3]) : "r"(a));
}
static __device__ __forceinline__ uint32_t s2u(const void* p) {
    uint32_t a;
    asm("{ .reg .u64 t; cvta.to.shared.u64 t, %1; cvt.u32.u64 %0, t; }"
        : "=r"(a) : "l"(p));
    return a;
}
static __device__ __forceinline__ void cpa16(uint32_t dst, const void* src) {
    asm volatile("cp.async.cg.shared.global [%0], [%1], 16;"
                 :: "r"(dst), "l"(src));
}
static __device__ __forceinline__ void cp_commit() {
    asm volatile("cp.async.commit_group;");
}
template<int N>
static __device__ __forceinline__ void cp_wait() {
    asm volatile("cp.async.wait_group %0;" :: "n"(N));
}
// exp2 of two fp32 values via packed fp16: result is a ready PV A-fragment half2
static __device__ __forceinline__ uint32_t exp2_f16x2(float lo, float hi) {
    uint32_t h, r;
    asm("cvt.rn.f16x2.f32 %0, %1, %2;" : "=r"(h) : "f"(hi), "f"(lo));
    asm("ex2.approx.f16x2 %0, %1;" : "=r"(r) : "r"(h));
    return r;
}

// ---------------- convert / transpose kernels --------------------------------
__global__ void xhalf_kernel(const float4* __restrict__ x,
                             __half2* __restrict__ xh, int n4)
{
    int i = blockIdx.x * blockDim.x + threadIdx.x;
    if (i >= n4) return;
    float4 v = x[i];
    xh[2*i]   = __floats2half2_rn(v.x, v.y);
    xh[2*i+1] = __floats2half2_rn(v.z, v.w);
}

__global__ void wtrans4_kernel(const float* __restrict__ W0,
                               const float* __restrict__ W1,
                               const float* __restrict__ W2,
                               const float* __restrict__ W3,
                               __half* __restrict__ wh)
{
    __shared__ float t[32][33];
    const float* Ws[4] = {W0, W1, W2, W3};
    const int z = blockIdx.z;
    const float* W = Ws[z];
    __half* th = wh + (size_t)z * DD * DD;

    const int n0 = blockIdx.x * 32, k0 = blockIdx.y * 32;
    const int tx = threadIdx.x, ty = threadIdx.y;
#pragma unroll
    for (int i = 0; i < 32; i += 8)
        t[ty + i][tx] = W[(size_t)(k0 + ty + i) * DD + n0 + tx];
    __syncthreads();
#pragma unroll
    for (int i = 0; i < 32; i += 8) {
        size_t o = (size_t)(n0 + ty + i) * DD + k0 + tx;
        th[o] = __float2half_rn(t[tx][ty + i]);
    }
}

// ---------------- fused fp16 mma.sync GEMM ------------------------------------
// sel = sel_base + blockIdx.x/8:
//   0: x@Wq*SC_SCALE -> qh   1: x@Wk -> kh   2: x@Wv -> vh
//   3: ctx@Wo+bias -> outF
#define ALD2 72
#define G_MAT2 (128*ALD2)
#define NSTG 16
#define GEMM_SMEM (2 * 3 * G_MAT2 * 2)          /* 110592 bytes */

__global__ __launch_bounds__(256, 2)
void gemm_fused(const __half* __restrict__ A, const __half* __restrict__ wh,
                const float* __restrict__ bias,
                __half* __restrict__ qh, __half* __restrict__ kh,
                __half* __restrict__ vh, float* __restrict__ outF,
                int sel_base)
{
    extern __shared__ char smg[];
    const uint32_t asu = s2u(smg);
    const uint32_t bsu = asu + 3 * G_MAT2 * 2;

    const int t = threadIdx.x;
    const int wid = t >> 5, lane = t & 31;
    const int wm = wid & 1, wn = wid >> 1;
    const int g = lane >> 2, qd = lane & 3;
    const int qd2 = qd * 2;
    const int sel = sel_base + (blockIdx.x >> 3);
    const int n0 = (blockIdx.x & 7) * 128;
    const int m0 = blockIdx.y * 128;

    const __half* B = wh + (size_t)sel * DD * DD;

    const int ld_row = t >> 3;
    const int ld_col = (t & 7) * 8;

    const int a_r = wm*64 + (lane & 15);
    const int a_c = (lane >> 4) * 8;
    const int b_r = wn*32 + (lane & 7) + ((lane >> 4) << 3);
    const int b_c = ((lane >> 3) & 1) * 8;

    float acc[4][4][4];
#pragma unroll
    for (int i = 0; i < 4; i++)
#pragma unroll
        for (int j = 0; j < 4; j++)
#pragma unroll
            for (int e = 0; e < 4; e++) acc[i][j][e] = 0.f;

    auto issue = [&](int s) {
        const int st = s % 3;
        const int kc = s * 64;
#pragma unroll
        for (int i = 0; i < 4; i++) {
            const int row = ld_row + i*32;
            const uint32_t so = (uint32_t)(st*G_MAT2 + row*ALD2 + ld_col) * 2;
            cpa16(asu + so, A + (size_t)(m0 + row) * DD + kc + ld_col);
            cpa16(bsu + so, B + (size_t)(n0 + row) * DD + kc + ld_col);
        }
        cp_commit();
    };

    issue(0);
    issue(1);

    for (int s = 0; s < NSTG; s++) {
        const int st = s % 3;
        if (s == NSTG - 1) cp_wait<0>();
        else               cp_wait<1>();
        __syncthreads();

        const uint32_t ab = asu + (uint32_t)(st*G_MAT2)*2;
        const uint32_t bb = bsu + (uint32_t)(st*G_MAT2)*2;
#pragma unroll
        for (int kk = 0; kk < 4; kk++) {
            uint32_t a[4][4], b4[2][4];
#pragma unroll
            for (int i = 0; i < 4; i++)
                ldsm4(a[i], ab + (uint32_t)((a_r + i*16)*ALD2 + kk*16 + a_c)*2);
#pragma unroll
            for (int jp = 0; jp < 2; jp++)
                ldsm4(b4[jp], bb + (uint32_t)((b_r + jp*16)*ALD2 + kk*16 + b_c)*2);
#pragma unroll
            for (int i = 0; i < 4; i++)
#pragma unroll
                for (int j = 0; j < 4; j++)
                    mma_f16(acc[i][j], a[i], &b4[j >> 1][(j & 1) * 2]);
        }
        if (s + 2 < NSTG) issue(s + 2);
    }

    // epilogue
    __half* oH = (sel == 0) ? qh : ((sel == 1) ? kh : vh);
    const float f = (sel == 0) ? SC_SCALE : 1.0f;   // fold softmax scale into Q
#pragma unroll
    for (int i = 0; i < 4; i++) {
        const int r1 = m0 + wm*64 + i*16 + g;
        const int r2 = r1 + 8;
#pragma unroll
        for (int j = 0; j < 4; j++) {
            const int col = n0 + wn*32 + j*8 + qd2;
            const float v0 = acc[i][j][0], v1 = acc[i][j][1];
            const float v2 = acc[i][j][2], v3 = acc[i][j][3];
            if (sel == 3) {
                float2 o1, o2;
                o1.x = v0 + bias[col]; o1.y = v1 + bias[col+1];
                o2.x = v2 + bias[col]; o2.y = v3 + bias[col+1];
                *(float2*)(outF + (size_t)r1 * DD + col) = o1;
                *(float2*)(outF + (size_t)r2 * DD + col) = o2;
            } else {
                *(__half2*)(oH + (size_t)r1 * DD + col) =
                    __floats2half2_rn(v0*f, v1*f);
                *(__half2*)(oH + (size_t)r2 * DD + col) =
                    __floats2half2_rn(v2*f, v3*f);
            }
        }
    }
}

// ---------------- causal flash attention (fp16 mma, 128-key stages) -----------
// 128 q-rows, 256 threads, 2 CTAs/SM. Q single fp16 (pre-scaled) in regs.
// Stage = 128 keys (K+V), 3-stage cp.async ring -> one barrier per 128 keys.
// Diagonal tiles: warp-level jplim skips fully-masked 16-key blocks.
#define FLD 72
#define ST_HALF (64*FLD*2)                    /* 9216: 64-key half, one matrix */
#define ST_MAT  (2*ST_HALF)                   /* 18432: 128-key K or V tile */
#define ST_BYTES (2*ST_MAT)                   /* 36864: K+V per stage */
#define FLASH_SMEM (3*ST_BYTES)               /* 110592 */

__global__ __launch_bounds__(256, 2)
void flash_mma(const __half* __restrict__ Qh, const __half* __restrict__ Kh,
               const __half* __restrict__ Vh, __half* __restrict__ Ch)
{
    extern __shared__ char smc[];
    const uint32_t smu = s2u(smc);

    const int t = threadIdx.x;
    const int w = t >> 5, lane = t & 31;
    const int g = lane >> 2, qd = lane & 3;
    const int qd2 = qd * 2;
    const int qb = (gridDim.x - 1) - blockIdx.x;   // heavy tiles first
    const int h = blockIdx.y, b = blockIdx.z;

    const size_t qrow0 = (size_t)b * SS + qb * 128;
    const size_t krow0 = (size_t)b * SS;
    const int hc = h * HDIM;
    const int smax = qb;                     // stages of 128 keys: 0..qb

    const int qa_r = 16*w + (lane & 15);
    const int qa_c = (lane >> 4) * 8;
    const int kb_r = (lane & 7) + ((lane >> 4) << 3);
    const int kb_c = ((lane >> 3) & 1) * 8;
    const int v_r  = (lane & 7) + (((lane >> 3) & 1) << 3);
    const int v_c  = (lane >> 4) * 8;

    // ---- Q staging: 128 rows x 128 B = 1024 chunks of 16B (4 sweeps) ----
#pragma unroll
    for (int i = 0; i < 4; i++) {
        const int idx = t + 256*i;              // 0..1023
        const int row = idx >> 3, col = (idx & 7) * 8;
        cpa16(smu + (uint32_t)(row*FLD + col)*2, Qh + (qrow0 + row)*DD + hc + col);
    }
    cp_commit();
    cp_wait<0>();
    __syncthreads();

    uint32_t qa[4][4];
#pragma unroll
    for (int s = 0; s < 4; s++)
        ldsm4(qa[s], smu + (uint32_t)(qa_r*FLD + s*16 + qa_c)*2);
    __syncthreads();

    auto issue_kv = [&](int s) {
        const uint32_t sb = smu + (s % 3)*ST_BYTES;
#pragma unroll
        for (int i = 0; i < 4; i++) {
            const int idx = t + 256*i;          // 0..1023 -> 128 rows
            const int row = idx >> 3, col = (idx & 7) * 8;
            const uint32_t so = (uint32_t)(row*FLD + col) * 2;
            const size_t gr = (krow0 + (size_t)s*128 + row)*DD + hc + col;
            cpa16(sb + so,          Kh + gr);
            cpa16(sb + ST_MAT + so, Vh + gr);
        }
        cp_commit();
    };
    issue_kv(0);
    if (smax >= 1) issue_kv(1);

    float sc[8][4], o[8][4];
#pragma unroll
    for (int j = 0; j < 8; j++)
#pragma unroll
        for (int e = 0; e < 4; e++) o[j][e] = 0.f;
    const float NEG_INF = __int_as_float(0xff800000u);
    float m0 = NEG_INF, m1 = NEG_INF, l0 = 0.f, l1 = 0.f;

    const int grow0 = qb*128 + 16*w + g;
    const int grow1 = grow0 + 8;
    const int wrow_max = qb*128 + 16*w + 15;

    const uint32_t ones2 = 0x3C003C00u;       // half2(1, 1)
    const uint32_t onesb[2] = {ones2, ones2};

    for (int s = 0; s <= smax; s++) {
        if (s == smax) cp_wait<0>();
        else           cp_wait<1>();
        __syncthreads();
        if (s + 2 <= smax) issue_kv(s + 2);   // stage (s+2)%3: retired in iter s-1

        const uint32_t stg = smu + (s % 3)*ST_BYTES;
#pragma unroll
        for (int h2 = 0; h2 < 2; h2++) {
            const int kb = 2*s + h2;
            if (kb*64 > wrow_max) break;       // this and later halves masked
            const uint32_t skh = stg + h2*ST_HALF;
            const uint32_t svb = stg + ST_MAT + h2*ST_HALF;

            // jplim: 16-key blocks that contain any unmasked key (warp-level)
            int jplim = 4;
            const int rel = wrow_max - kb*64;
            if (rel < 48) jplim = (rel >> 4) + 1;

#pragma unroll
            for (int j = 0; j < 8; j++)
#pragma unroll
                for (int e = 0; e < 4; e++) sc[j][e] = 0.f;

#pragma unroll
            for (int ss = 0; ss < 4; ss++) {
#pragma unroll
                for (int jp = 0; jp < 4; jp++) {
                    if (jp < jplim) {
                        uint32_t bh[4];
                        ldsm4(bh, skh +
                              (uint32_t)((jp*16 + kb_r)*FLD + ss*16 + kb_c)*2);
                        mma_f16(sc[2*jp  ], qa[ss], bh);
                        mma_f16(sc[2*jp+1], qa[ss], bh + 2);
                    }
                }
            }

            // ---- causal mask + row max (scale pre-folded into Q) ----
            const bool diag = (kb >= 2*qb);
            float mx0 = NEG_INF, mx1 = NEG_INF;
#pragma unroll
            for (int j = 0; j < 8; j++) {
                if (diag) {
                    const int c0 = kb*64 + j*8 + qd2, c1 = c0 + 1;
                    if (c0 > grow0) sc[j][0] = NEG_INF;
                    if (c1 > grow0) sc[j][1] = NEG_INF;
                    if (c0 > grow1) sc[j][2] = NEG_INF;
                    if (c1 > grow1) sc[j][3] = NEG_INF;
                }
                mx0 = fmaxf(mx0, fmaxf(sc[j][0], sc[j][1]));
                mx1 = fmaxf(mx1, fmaxf(sc[j][2], sc[j][3]));
            }
            mx0 = fmaxf(mx0, __shfl_xor_sync(0xffffffffu, mx0, 1));
            mx0 = fmaxf(mx0, __shfl_xor_sync(0xffffffffu, mx0, 2));
            mx1 = fmaxf(mx1, __shfl_xor_sync(0xffffffffu, mx1, 1));
            mx1 = fmaxf(mx1, __shfl_xor_sync(0xffffffffu, mx1, 2));

            const float mn0 = fmaxf(m0, mx0), mn1 = fmaxf(m1, mx1);
            const float al0 = exp2f(m0 - mn0), al1 = exp2f(m1 - mn1);
            m0 = mn0; m1 = mn1;

            // ---- p = exp2(s - m) in packed fp16 (ready PV fragments) ----
            uint32_t pf[8][2];
#pragma unroll
            for (int j = 0; j < 8; j++) {
                if (j < 2*jplim) {
                    pf[j][0] = exp2_f16x2(sc[j][0] - mn0, sc[j][1] - mn0);
                    pf[j][1] = exp2_f16x2(sc[j][2] - mn1, sc[j][3] - mn1);
                }
            }

            // ---- rescale o ----
#pragma unroll
            for (int j = 0; j < 8; j++) {
                o[j][0] *= al0; o[j][1] *= al0;
                o[j][2] *= al1; o[j][3] *= al1;
            }

            // ---- PV + row-sum (ones column), skipping masked key groups ----
            float lacc[4] = {0.f, 0.f, 0.f, 0.f};
#pragma unroll
            for (int ss = 0; ss < 4; ss++) {
                if (ss < jplim) {
                    uint32_t a[4];
                    a[0] = pf[2*ss  ][0]; a[1] = pf[2*ss  ][1];
                    a[2] = pf[2*ss+1][0]; a[3] = pf[2*ss+1][1];
                    mma_f16(lacc, a, onesb);
#pragma unroll
                    for (int jp = 0; jp < 4; jp++) {
                        uint32_t bv[4];
                        ldsm4t(bv, svb +
                               (uint32_t)((ss*16 + v_r)*FLD + jp*16 + v_c)*2);
                        mma_f16(o[2*jp  ], a, bv);
                        mma_f16(o[2*jp+1], a, bv + 2);
                    }
                }
            }
            l0 = l0 * al0 + lacc[0];
            l1 = l1 * al1 + lacc[2];
        }
    }

    // ---- epilogue ----
    const float inv0 = 1.f / l0, inv1 = 1.f / l1;
    const size_t r1 = qrow0 + 16*w + g;
    const size_t r2 = r1 + 8;
#pragma unroll
    for (int j = 0; j < 8; j++) {
        const int col = hc + j*8 + qd2;
        *(__half2*)(Ch + r1*DD + col) =
            __floats2half2_rn(o[j][0]*inv0, o[j][1]*inv0);
        *(__half2*)(Ch + r2*DD + col) =
            __floats2half2_rn(o[j][2]*inv1, o[j][3]*inv1);
    }
}

// ---------------------------------------------------------------------------
extern "C" void kernel_launch(void* const* d_in, const int* in_sizes, int n_in,
                              void* d_out, int out_size)
{
    const float* x  = (const float*)d_in[0];
    const float* Wq = (const float*)d_in[1];
    const float* Wk = (const float*)d_in[2];
    const float* Wv = (const float*)d_in[3];
    const float* Wo = (const float*)d_in[4];
    const float* bo = (const float*)d_in[5];
    float* out = (float*)d_out;

    __half *xh, *qh, *kh, *vh, *ch, *wh;
    cudaGetSymbolAddress((void**)&xh, g_xh);
    cudaGetSymbolAddress((void**)&qh, g_qh);
    cudaGetSymbolAddress((void**)&kh, g_kh);
    cudaGetSymbolAddress((void**)&vh, g_vh);
    cudaGetSymbolAddress((void**)&ch, g_ch);
    cudaGetSymbolAddress((void**)&wh, g_wh);

    cudaFuncSetAttribute(gemm_fused,
                         cudaFuncAttributeMaxDynamicSharedMemorySize, GEMM_SMEM);
    cudaFuncSetAttribute(flash_mma,
                         cudaFuncAttributeMaxDynamicSharedMemorySize, FLASH_SMEM);

    // weight transpose + fp16 convert
    dim3 wb(32, 8), wg(DD/32, DD/32, 4);
    wtrans4_kernel<<<wg, wb>>>(Wq, Wk, Wv, Wo, wh);

    // x -> fp16
    const int n4 = MROWS * DD / 4;
    xhalf_kernel<<<n4 / 256, 256>>>((const float4*)x, (__half2*)xh, n4);

    // fused QKV projections
    dim3 gq(3 * DD / 128, MROWS / 128);   // (24, 64)
    gemm_fused<<<gq, 256, GEMM_SMEM>>>(xh, wh, nullptr,
                                       qh, kh, vh, nullptr, 0);

    // attention
    dim3 gf(SS / 128, NH, BB);            // (16, 16, 4)
    flash_mma<<<gf, 256, FLASH_SMEM>>>(qh, kh, vh, ch);

    // output projection + bias
    dim3 go(DD / 128, MROWS / 128);       // (8, 64)
    gemm_fused<<<go, 256, GEMM_SMEM>>>(ch, wh, bo,
                                       nullptr, nullptr, nullptr, out, 3);
}

// round 14
// speedup vs baseline: 1.0224x; 1.0224x over previous
#include <cuda_runtime.h>
#include <cuda_bf16.h>
#include <cuda_fp16.h>
#include <math.h>
#include <stdint.h>

#define BB 4
#define SS 2048
#define DD 1024
#define NH 16
#define HDIM 64
#define MROWS (BB*SS)   /* 8192 */

#define SC_SCALE 0.180336880f   /* 0.125 * log2(e), folded into Q projection */

// ---------------- scratch (__device__ globals; allocs forbidden) ------------
__device__ __half g_xh[MROWS*DD];
__device__ __half g_qh[MROWS*DD];
__device__ __half g_kh[MROWS*DD];
__device__ __half g_vh[MROWS*DD];
__device__ __half g_ch[MROWS*DD];
__device__ __half g_wh[4][DD*DD];   // transposed fp16: [Wq, Wk, Wv, Wo]

// ---------------- ptx helpers -------------------------------------------------
static __device__ __forceinline__ void mma_f16(float* c, const uint32_t* a,
                                               const uint32_t* b) {
    asm volatile(
        "mma.sync.aligned.m16n8k16.row.col.f32.f16.f16.f32 "
        "{%0,%1,%2,%3}, {%4,%5,%6,%7}, {%8,%9}, {%0,%1,%2,%3};"
        : "+f"(c[0]), "+f"(c[1]), "+f"(c[2]), "+f"(c[3])
        : "r"(a[0]), "r"(a[1]), "r"(a[2]), "r"(a[3]), "r"(b[0]), "r"(b[1]));
}
static __device__ __forceinline__ void ldsm4(uint32_t* r, uint32_t a) {
    asm volatile("ldmatrix.sync.aligned.m8n8.x4.shared.b16 {%0,%1,%2,%3}, [%4];"
                 : "=r"(r[0]), "=r"(r[1]), "=r"(r[2]), "=r"(r[3]) : "r"(a));
}
static __device__ __forceinline__ void ldsm4t(uint32_t* r, uint32_t a) {
    asm volatile("ldmatrix.sync.aligned.m8n8.x4.trans.shared.b16 {%0,%1,%2,%3}, [%4];"
                 : "=r"(r[0]), "=r"(r[1]), "=r"(r[2]), "=r"(r[3]) : "r"(a));
}
static __device__ __forceinline__ uint32_t s2u(const void* p) {
    uint32_t a;
    asm("{ .reg .u64 t; cvta.to.shared.u64 t, %1; cvt.u32.u64 %0, t; }"
        : "=r"(a) : "l"(p));
    return a;
}
static __device__ __forceinline__ void cpa16(uint32_t dst, const void* src) {
    asm volatile("cp.async.cg.shared.global [%0], [%1], 16;"
                 :: "r"(dst), "l"(src));
}
static __device__ __forceinline__ void cp_commit() {
    asm volatile("cp.async.commit_group;");
}
template<int N>
static __device__ __forceinline__ void cp_wait() {
    asm volatile("cp.async.wait_group %0;" :: "n"(N));
}
// exp2 of two fp32 values via packed fp16: result is a ready PV A-fragment half2
static __device__ __forceinline__ uint32_t exp2_f16x2(float lo, float hi) {
    uint32_t h, r;
    asm("cvt.rn.f16x2.f32 %0, %1, %2;" : "=r"(h) : "f"(hi), "f"(lo));
    asm("ex2.approx.f16x2 %0, %1;" : "=r"(r) : "r"(h));
    return r;
}

// ---------------- convert / transpose kernels --------------------------------
__global__ void xhalf_kernel(const float4* __restrict__ x,
                             __half2* __restrict__ xh, int n4)
{
    int i = blockIdx.x * blockDim.x + threadIdx.x;
    if (i >= n4) return;
    float4 v = x[i];
    xh[2*i]   = __floats2half2_rn(v.x, v.y);
    xh[2*i+1] = __floats2half2_rn(v.z, v.w);
}

__global__ void wtrans4_kernel(const float* __restrict__ W0,
                               const float* __restrict__ W1,
                               const float* __restrict__ W2,
                               const float* __restrict__ W3,
                               __half* __restrict__ wh)
{
    __shared__ float t[32][33];
    const float* Ws[4] = {W0, W1, W2, W3};
    const int z = blockIdx.z;
    const float* W = Ws[z];
    __half* th = wh + (size_t)z * DD * DD;

    const int n0 = blockIdx.x * 32, k0 = blockIdx.y * 32;
    const int tx = threadIdx.x, ty = threadIdx.y;
#pragma unroll
    for (int i = 0; i < 32; i += 8)
        t[ty + i][tx] = W[(size_t)(k0 + ty + i) * DD + n0 + tx];
    __syncthreads();
#pragma unroll
    for (int i = 0; i < 32; i += 8) {
        size_t o = (size_t)(n0 + ty + i) * DD + k0 + tx;
        th[o] = __float2half_rn(t[tx][ty + i]);
    }
}

// ---------------- fused fp16 mma.sync GEMM ------------------------------------
// sel = sel_base + blockIdx.x/8:
//   0: x@Wq*SC_SCALE -> qh   1: x@Wk -> kh   2: x@Wv -> vh
//   3: ctx@Wo+bias -> outF
#define ALD2 72
#define G_MAT2 (128*ALD2)
#define NSTG 16
#define GEMM_SMEM (2 * 3 * G_MAT2 * 2)          /* 110592 bytes */

__global__ __launch_bounds__(256, 2)
void gemm_fused(const __half* __restrict__ A, const __half* __restrict__ wh,
                const float* __restrict__ bias,
                __half* __restrict__ qh, __half* __restrict__ kh,
                __half* __restrict__ vh, float* __restrict__ outF,
                int sel_base)
{
    extern __shared__ char smg[];
    const uint32_t asu = s2u(smg);
    const uint32_t bsu = asu + 3 * G_MAT2 * 2;

    const int t = threadIdx.x;
    const int wid = t >> 5, lane = t & 31;
    const int wm = wid & 1, wn = wid >> 1;
    const int g = lane >> 2, qd = lane & 3;
    const int qd2 = qd * 2;
    const int sel = sel_base + (blockIdx.x >> 3);
    const int n0 = (blockIdx.x & 7) * 128;
    const int m0 = blockIdx.y * 128;

    const __half* B = wh + (size_t)sel * DD * DD;

    const int ld_row = t >> 3;
    const int ld_col = (t & 7) * 8;

    const int a_r = wm*64 + (lane & 15);
    const int a_c = (lane >> 4) * 8;
    const int b_r = wn*32 + (lane & 7) + ((lane >> 4) << 3);
    const int b_c = ((lane >> 3) & 1) * 8;

    float acc[4][4][4];
#pragma unroll
    for (int i = 0; i < 4; i++)
#pragma unroll
        for (int j = 0; j < 4; j++)
#pragma unroll
            for (int e = 0; e < 4; e++) acc[i][j][e] = 0.f;

    auto issue = [&](int s) {
        const int st = s % 3;
        const int kc = s * 64;
#pragma unroll
        for (int i = 0; i < 4; i++) {
            const int row = ld_row + i*32;
            const uint32_t so = (uint32_t)(st*G_MAT2 + row*ALD2 + ld_col) * 2;
            cpa16(asu + so, A + (size_t)(m0 + row) * DD + kc + ld_col);
            cpa16(bsu + so, B + (size_t)(n0 + row) * DD + kc + ld_col);
        }
        cp_commit();
    };

    issue(0);
    issue(1);

    for (int s = 0; s < NSTG; s++) {
        const int st = s % 3;
        if (s == NSTG - 1) cp_wait<0>();
        else               cp_wait<1>();
        __syncthreads();
        if (s + 2 < NSTG) issue(s + 2);   // stage (s-1)%3: reads retired by barrier

        const uint32_t ab = asu + (uint32_t)(st*G_MAT2)*2;
        const uint32_t bb = bsu + (uint32_t)(st*G_MAT2)*2;
#pragma unroll
        for (int kk = 0; kk < 4; kk++) {
            uint32_t a[4][4], b4[2][4];
#pragma unroll
            for (int i = 0; i < 4; i++)
                ldsm4(a[i], ab + (uint32_t)((a_r + i*16)*ALD2 + kk*16 + a_c)*2);
#pragma unroll
            for (int jp = 0; jp < 2; jp++)
                ldsm4(b4[jp], bb + (uint32_t)((b_r + jp*16)*ALD2 + kk*16 + b_c)*2);
#pragma unroll
            for (int i = 0; i < 4; i++)
#pragma unroll
                for (int j = 0; j < 4; j++)
                    mma_f16(acc[i][j], a[i], &b4[j >> 1][(j & 1) * 2]);
        }
    }

    // epilogue
    __half* oH = (sel == 0) ? qh : ((sel == 1) ? kh : vh);
    const float f = (sel == 0) ? SC_SCALE : 1.0f;   // fold softmax scale into Q
#pragma unroll
    for (int i = 0; i < 4; i++) {
        const int r1 = m0 + wm*64 + i*16 + g;
        const int r2 = r1 + 8;
#pragma unroll
        for (int j = 0; j < 4; j++) {
            const int col = n0 + wn*32 + j*8 + qd2;
            const float v0 = acc[i][j][0], v1 = acc[i][j][1];
            const float v2 = acc[i][j][2], v3 = acc[i][j][3];
            if (sel == 3) {
                float2 o1, o2;
                o1.x = v0 + bias[col]; o1.y = v1 + bias[col+1];
                o2.x = v2 + bias[col]; o2.y = v3 + bias[col+1];
                *(float2*)(outF + (size_t)r1 * DD + col) = o1;
                *(float2*)(outF + (size_t)r2 * DD + col) = o2;
            } else {
                *(__half2*)(oH + (size_t)r1 * DD + col) =
                    __floats2half2_rn(v0*f, v1*f);
                *(__half2*)(oH + (size_t)r2 * DD + col) =
                    __floats2half2_rn(v2*f, v3*f);
            }
        }
    }
}

// ---------------- causal flash attention (fp16 mma, f16x2 softmax) ------------
// Round-12 structure: 64-key stages, tile-level masked skip only.
// cp.async for stage kb+2 issued right after the barrier (before compute).
#define FLD 72
#define ST_ONE  (64*FLD*2)                    /* 9216  */
#define ST_BYTES (2*ST_ONE)                   /* 18432: K + V per stage */
#define FLASH_SMEM (3*ST_BYTES)               /* 55296 */

__global__ __launch_bounds__(256, 2)
void flash_mma(const __half* __restrict__ Qh, const __half* __restrict__ Kh,
               const __half* __restrict__ Vh, __half* __restrict__ Ch)
{
    extern __shared__ char smc[];
    const uint32_t smu = s2u(smc);

    const int t = threadIdx.x;
    const int w = t >> 5, lane = t & 31;
    const int g = lane >> 2, qd = lane & 3;
    const int qd2 = qd * 2;
    const int qb = (gridDim.x - 1) - blockIdx.x;
    const int h = blockIdx.y, b = blockIdx.z;

    const size_t qrow0 = (size_t)b * SS + qb * 128;
    const size_t krow0 = (size_t)b * SS;
    const int hc = h * HDIM;
    const int kbmax = 2*qb + 1;

    const int qa_r = 16*w + (lane & 15);
    const int qa_c = (lane >> 4) * 8;
    const int kb_r = (lane & 7) + ((lane >> 4) << 3);
    const int kb_c = ((lane >> 3) & 1) * 8;
    const int v_r  = (lane & 7) + (((lane >> 3) & 1) << 3);
    const int v_c  = (lane >> 4) * 8;

    // ---- Q staging: 128 rows x 128 B = 1024 chunks of 16B (4 sweeps) ----
#pragma unroll
    for (int i = 0; i < 4; i++) {
        const int idx = t + 256*i;              // 0..1023
        const int row = idx >> 3, col = (idx & 7) * 8;
        cpa16(smu + (uint32_t)(row*FLD + col)*2, Qh + (qrow0 + row)*DD + hc + col);
    }
    cp_commit();
    cp_wait<0>();
    __syncthreads();

    uint32_t qa[4][4];
#pragma unroll
    for (int s = 0; s < 4; s++)
        ldsm4(qa[s], smu + (uint32_t)(qa_r*FLD + s*16 + qa_c)*2);
    __syncthreads();

    auto issue_kv = [&](int kb) {
        const uint32_t sb = smu + (kb % 3)*ST_BYTES;
#pragma unroll
        for (int i = 0; i < 2; i++) {
            const int idx = t + 256*i;
            const int row = idx >> 3, col = (idx & 7) * 8;
            const uint32_t so = (uint32_t)(row*FLD + col) * 2;
            const size_t gr = (krow0 + kb*64 + row)*DD + hc + col;
            cpa16(sb + so,          Kh + gr);
            cpa16(sb + ST_ONE + so, Vh + gr);
        }
        cp_commit();
    };
    issue_kv(0);
    issue_kv(1);

    float sc[8][4], o[8][4];
#pragma unroll
    for (int j = 0; j < 8; j++)
#pragma unroll
        for (int e = 0; e < 4; e++) o[j][e] = 0.f;
    const float NEG_INF = __int_as_float(0xff800000u);
    float m0 = NEG_INF, m1 = NEG_INF, l0 = 0.f, l1 = 0.f;

    const int grow0 = qb*128 + 16*w + g;
    const int grow1 = grow0 + 8;
    const int wrow_max = qb*128 + 16*w + 15;

    const uint32_t ones2 = 0x3C003C00u;       // half2(1, 1)
    const uint32_t onesb[2] = {ones2, ones2};

    for (int kb = 0; kb <= kbmax; kb++) {
        const int st = kb % 3;
        if (kb == kbmax) cp_wait<0>();
        else             cp_wait<1>();
        __syncthreads();
        if (kb + 2 <= kbmax) issue_kv(kb + 2);   // stage (kb-1)%3: retired

        const bool active = (kb*64 <= wrow_max);
        if (active) {
            const uint32_t skh = smu + st*ST_BYTES;
            const uint32_t svb = skh + ST_ONE;

#pragma unroll
            for (int j = 0; j < 8; j++)
#pragma unroll
                for (int e = 0; e < 4; e++) sc[j][e] = 0.f;

#pragma unroll
            for (int s = 0; s < 4; s++) {
#pragma unroll
                for (int jp = 0; jp < 4; jp++) {
                    uint32_t bh[4];
                    ldsm4(bh, skh +
                          (uint32_t)((jp*16 + kb_r)*FLD + s*16 + kb_c)*2);
                    mma_f16(sc[2*jp  ], qa[s], bh);
                    mma_f16(sc[2*jp+1], qa[s], bh + 2);
                }
            }

            // ---- causal mask + row max (scale pre-folded into Q) ----
            const bool diag = (kb >= 2*qb);
            float mx0 = NEG_INF, mx1 = NEG_INF;
#pragma unroll
            for (int j = 0; j < 8; j++) {
                if (diag) {
                    const int c0 = kb*64 + j*8 + qd2, c1 = c0 + 1;
                    if (c0 > grow0) sc[j][0] = NEG_INF;
                    if (c1 > grow0) sc[j][1] = NEG_INF;
                    if (c0 > grow1) sc[j][2] = NEG_INF;
                    if (c1 > grow1) sc[j][3] = NEG_INF;
                }
                mx0 = fmaxf(mx0, fmaxf(sc[j][0], sc[j][1]));
                mx1 = fmaxf(mx1, fmaxf(sc[j][2], sc[j][3]));
            }
            mx0 = fmaxf(mx0, __shfl_xor_sync(0xffffffffu, mx0, 1));
            mx0 = fmaxf(mx0, __shfl_xor_sync(0xffffffffu, mx0, 2));
            mx1 = fmaxf(mx1, __shfl_xor_sync(0xffffffffu, mx1, 1));
            mx1 = fmaxf(mx1, __shfl_xor_sync(0xffffffffu, mx1, 2));

            const float mn0 = fmaxf(m0, mx0), mn1 = fmaxf(m1, mx1);
            const float al0 = exp2f(m0 - mn0), al1 = exp2f(m1 - mn1);
            m0 = mn0; m1 = mn1;

            // ---- p = exp2(s - m) in packed fp16 (ready PV fragments) ----
            uint32_t pf[8][2];
#pragma unroll
            for (int j = 0; j < 8; j++) {
                pf[j][0] = exp2_f16x2(sc[j][0] - mn0, sc[j][1] - mn0);
                pf[j][1] = exp2_f16x2(sc[j][2] - mn1, sc[j][3] - mn1);
            }

            // ---- rescale o ----
#pragma unroll
            for (int j = 0; j < 8; j++) {
                o[j][0] *= al0; o[j][1] *= al0;
                o[j][2] *= al1; o[j][3] *= al1;
            }

            // ---- PV + row-sum (ones column) ----
            float lacc[4] = {0.f, 0.f, 0.f, 0.f};
#pragma unroll
            for (int s = 0; s < 4; s++) {
                uint32_t a[4];
                a[0] = pf[2*s  ][0]; a[1] = pf[2*s  ][1];
                a[2] = pf[2*s+1][0]; a[3] = pf[2*s+1][1];
                mma_f16(lacc, a, onesb);       // exact fp32 row sums of fp16 P
#pragma unroll
                for (int jp = 0; jp < 4; jp++) {
                    uint32_t bv[4];
                    ldsm4t(bv, svb + (uint32_t)((s*16 + v_r)*FLD + jp*16 + v_c)*2);
                    mma_f16(o[2*jp  ], a, bv);
                    mma_f16(o[2*jp+1], a, bv + 2);
                }
            }
            l0 = l0 * al0 + lacc[0];
            l1 = l1 * al1 + lacc[2];
        }
    }

    // ---- epilogue ----
    const float inv0 = 1.f / l0, inv1 = 1.f / l1;
    const size_t r1 = qrow0 + 16*w + g;
    const size_t r2 = r1 + 8;
#pragma unroll
    for (int j = 0; j < 8; j++) {
        const int col = hc + j*8 + qd2;
        *(__half2*)(Ch + r1*DD + col) =
            __floats2half2_rn(o[j][0]*inv0, o[j][1]*inv0);
        *(__half2*)(Ch + r2*DD + col) =
            __floats2half2_rn(o[j][2]*inv1, o[j][3]*inv1);
    }
}

// ---------------------------------------------------------------------------
extern "C" void kernel_launch(void* const* d_in, const int* in_sizes, int n_in,
                              void* d_out, int out_size)
{
    const float* x  = (const float*)d_in[0];
    const float* Wq = (const float*)d_in[1];
    const float* Wk = (const float*)d_in[2];
    const float* Wv = (const float*)d_in[3];
    const float* Wo = (const float*)d_in[4];
    const float* bo = (const float*)d_in[5];
    float* out = (float*)d_out;

    __half *xh, *qh, *kh, *vh, *ch, *wh;
    cudaGetSymbolAddress((void**)&xh, g_xh);
    cudaGetSymbolAddress((void**)&qh, g_qh);
    cudaGetSymbolAddress((void**)&kh, g_kh);
    cudaGetSymbolAddress((void**)&vh, g_vh);
    cudaGetSymbolAddress((void**)&ch, g_ch);
    cudaGetSymbolAddress((void**)&wh, g_wh);

    cudaFuncSetAttribute(gemm_fused,
                         cudaFuncAttributeMaxDynamicSharedMemorySize, GEMM_SMEM);
    cudaFuncSetAttribute(flash_mma,
                         cudaFuncAttributeMaxDynamicSharedMemorySize, FLASH_SMEM);

    // weight transpose + fp16 convert
    dim3 wb(32, 8), wg(DD/32, DD/32, 4);
    wtrans4_kernel<<<wg, wb>>>(Wq, Wk, Wv, Wo, wh);

    // x -> fp16
    const int n4 = MROWS * DD / 4;
    xhalf_kernel<<<n4 / 256, 256>>>((const float4*)x, (__half2*)xh, n4);

    // fused QKV projections
    dim3 gq(3 * DD / 128, MROWS / 128);   // (24, 64)
    gemm_fused<<<gq, 256, GEMM_SMEM>>>(xh, wh, nullptr,
                                       qh, kh, vh, nullptr, 0);

    // attention
    dim3 gf(SS / 128, NH, BB);            // (16, 16, 4)
    flash_mma<<<gf, 256, FLASH_SMEM>>>(qh, kh, vh, ch);

    // output projection + bias
    dim3 go(DD / 128, MROWS / 128);       // (8, 64)
    gemm_fused<<<go, 256, GEMM_SMEM>>>(ch, wh, bo,
                                       nullptr, nullptr, nullptr, out, 3);
}

// round 15
// speedup vs baseline: 1.0803x; 1.0565x over previous
#include <cuda_runtime.h>
#include <cuda_bf16.h>
#include <cuda_fp16.h>
#include <math.h>
#include <stdint.h>

#define BB 4
#define SS 2048
#define DD 1024
#define NH 16
#define HDIM 64
#define MROWS (BB*SS)   /* 8192 */

#define SC_SCALE 0.180336880f   /* 0.125 * log2(e), folded into Q projection */

// ---------------- scratch (__device__ globals; allocs forbidden) ------------
__device__ __half g_xh[MROWS*DD];
__device__ __half g_qh[MROWS*DD];
__device__ __half g_kh[MROWS*DD];
__device__ __half g_vh[MROWS*DD];
__device__ __half g_ch[MROWS*DD];
__device__ __half g_wh[4][DD*DD];   // transposed fp16: [Wq, Wk, Wv, Wo]

// ---------------- ptx helpers -------------------------------------------------
static __device__ __forceinline__ void mma_f16(float* c, const uint32_t* a,
                                               const uint32_t* b) {
    asm volatile(
        "mma.sync.aligned.m16n8k16.row.col.f32.f16.f16.f32 "
        "{%0,%1,%2,%3}, {%4,%5,%6,%7}, {%8,%9}, {%0,%1,%2,%3};"
        : "+f"(c[0]), "+f"(c[1]), "+f"(c[2]), "+f"(c[3])
        : "r"(a[0]), "r"(a[1]), "r"(a[2]), "r"(a[3]), "r"(b[0]), "r"(b[1]));
}
static __device__ __forceinline__ void ldsm4(uint32_t* r, uint32_t a) {
    asm volatile("ldmatrix.sync.aligned.m8n8.x4.shared.b16 {%0,%1,%2,%3}, [%4];"
                 : "=r"(r[0]), "=r"(r[1]), "=r"(r[2]), "=r"(r[3]) : "r"(a));
}
static __device__ __forceinline__ void ldsm4t(uint32_t* r, uint32_t a) {
    asm volatile("ldmatrix.sync.aligned.m8n8.x4.trans.shared.b16 {%0,%1,%2,%3}, [%4];"
                 : "=r"(r[0]), "=r"(r[1]), "=r"(r[2]), "=r"(r[3]) : "r"(a));
}
static __device__ __forceinline__ uint32_t s2u(const void* p) {
    uint32_t a;
    asm("{ .reg .u64 t; cvta.to.shared.u64 t, %1; cvt.u32.u64 %0, t; }"
        : "=r"(a) : "l"(p));
    return a;
}
static __device__ __forceinline__ void cpa16(uint32_t dst, const void* src) {
    asm volatile("cp.async.cg.shared.global [%0], [%1], 16;"
                 :: "r"(dst), "l"(src));
}
static __device__ __forceinline__ void cp_commit() {
    asm volatile("cp.async.commit_group;");
}
template<int N>
static __device__ __forceinline__ void cp_wait() {
    asm volatile("cp.async.wait_group %0;" :: "n"(N));
}
// exp2 of two fp32 values via packed fp16: result is a ready PV A-fragment half2
static __device__ __forceinline__ uint32_t exp2_f16x2(float lo, float hi) {
    uint32_t h, r;
    asm("cvt.rn.f16x2.f32 %0, %1, %2;" : "=r"(h) : "f"(hi), "f"(lo));
    asm("ex2.approx.f16x2 %0, %1;" : "=r"(r) : "r"(h));
    return r;
}

// ---------------- prep kernel: weight transpose (z<4) + x convert (z==4) -----
__global__ void prep_kernel(const float* __restrict__ W0,
                            const float* __restrict__ W1,
                            const float* __restrict__ W2,
                            const float* __restrict__ W3,
                            __half* __restrict__ wh,
                            const float4* __restrict__ x,
                            __half2* __restrict__ xh, int n4)
{
    __shared__ float t[32][33];
    const int z = blockIdx.z;
    const int tx = threadIdx.x, ty = threadIdx.y;   // 32 x 8

    if (z < 4) {
        const float* Ws[4] = {W0, W1, W2, W3};
        const float* W = Ws[z];
        __half* th = wh + (size_t)z * DD * DD;
        const int n0 = blockIdx.x * 32, k0 = blockIdx.y * 32;
#pragma unroll
        for (int i = 0; i < 32; i += 8)
            t[ty + i][tx] = W[(size_t)(k0 + ty + i) * DD + n0 + tx];
        __syncthreads();
#pragma unroll
        for (int i = 0; i < 32; i += 8) {
            size_t o = (size_t)(n0 + ty + i) * DD + k0 + tx;
            th[o] = __float2half_rn(t[tx][ty + i]);
        }
    } else {
        // x -> fp16: grid-stride over n4 float4s with 1024 blocks x 256 threads
        const int tid = (blockIdx.y * gridDim.x + blockIdx.x) * 256 + ty * 32 + tx;
        const int nthreads = gridDim.x * gridDim.y * 256;
        for (int i = tid; i < n4; i += nthreads) {
            float4 v = x[i];
            xh[2*i]   = __floats2half2_rn(v.x, v.y);
            xh[2*i+1] = __floats2half2_rn(v.z, v.w);
        }
    }
}

// ---------------- fused fp16 mma.sync GEMM ------------------------------------
// sel = sel_base + blockIdx.x/8:
//   0: x@Wq*SC_SCALE -> qh   1: x@Wk -> kh   2: x@Wv -> vh
//   3: ctx@Wo+bias -> outF
#define ALD2 72
#define G_MAT2 (128*ALD2)
#define NSTG 16
#define GEMM_SMEM (2 * 3 * G_MAT2 * 2)          /* 110592 bytes */

__global__ __launch_bounds__(256, 2)
void gemm_fused(const __half* __restrict__ A, const __half* __restrict__ wh,
                const float* __restrict__ bias,
                __half* __restrict__ qh, __half* __restrict__ kh,
                __half* __restrict__ vh, float* __restrict__ outF,
                int sel_base)
{
    extern __shared__ char smg[];
    const uint32_t asu = s2u(smg);
    const uint32_t bsu = asu + 3 * G_MAT2 * 2;

    const int t = threadIdx.x;
    const int wid = t >> 5, lane = t & 31;
    const int wm = wid & 1, wn = wid >> 1;
    const int g = lane >> 2, qd = lane & 3;
    const int qd2 = qd * 2;
    const int sel = sel_base + (blockIdx.x >> 3);
    const int n0 = (blockIdx.x & 7) * 128;
    const int m0 = blockIdx.y * 128;

    const __half* B = wh + (size_t)sel * DD * DD;

    const int ld_row = t >> 3;
    const int ld_col = (t & 7) * 8;

    const int a_r = wm*64 + (lane & 15);
    const int a_c = (lane >> 4) * 8;
    const int b_r = wn*32 + (lane & 7) + ((lane >> 4) << 3);
    const int b_c = ((lane >> 3) & 1) * 8;

    float acc[4][4][4];
#pragma unroll
    for (int i = 0; i < 4; i++)
#pragma unroll
        for (int j = 0; j < 4; j++)
#pragma unroll
            for (int e = 0; e < 4; e++) acc[i][j][e] = 0.f;

    auto issue = [&](int s) {
        const int st = s % 3;
        const int kc = s * 64;
#pragma unroll
        for (int i = 0; i < 4; i++) {
            const int row = ld_row + i*32;
            const uint32_t so = (uint32_t)(st*G_MAT2 + row*ALD2 + ld_col) * 2;
            cpa16(asu + so, A + (size_t)(m0 + row) * DD + kc + ld_col);
            cpa16(bsu + so, B + (size_t)(n0 + row) * DD + kc + ld_col);
        }
        cp_commit();
    };

    issue(0);
    issue(1);

    for (int s = 0; s < NSTG; s++) {
        const int st = s % 3;
        if (s == NSTG - 1) cp_wait<0>();
        else               cp_wait<1>();
        __syncthreads();

        const uint32_t ab = asu + (uint32_t)(st*G_MAT2)*2;
        const uint32_t bb = bsu + (uint32_t)(st*G_MAT2)*2;
#pragma unroll
        for (int kk = 0; kk < 4; kk++) {
            uint32_t a[4][4], b4[2][4];
#pragma unroll
            for (int i = 0; i < 4; i++)
                ldsm4(a[i], ab + (uint32_t)((a_r + i*16)*ALD2 + kk*16 + a_c)*2);
#pragma unroll
            for (int jp = 0; jp < 2; jp++)
                ldsm4(b4[jp], bb + (uint32_t)((b_r + jp*16)*ALD2 + kk*16 + b_c)*2);
#pragma unroll
            for (int i = 0; i < 4; i++)
#pragma unroll
                for (int j = 0; j < 4; j++)
                    mma_f16(acc[i][j], a[i], &b4[j >> 1][(j & 1) * 2]);
        }
        if (s + 2 < NSTG) issue(s + 2);   // r12 schedule: issue AFTER compute
    }

    // epilogue
    __half* oH = (sel == 0) ? qh : ((sel == 1) ? kh : vh);
    const float f = (sel == 0) ? SC_SCALE : 1.0f;   // fold softmax scale into Q
#pragma unroll
    for (int i = 0; i < 4; i++) {
        const int r1 = m0 + wm*64 + i*16 + g;
        const int r2 = r1 + 8;
#pragma unroll
        for (int j = 0; j < 4; j++) {
            const int col = n0 + wn*32 + j*8 + qd2;
            const float v0 = acc[i][j][0], v1 = acc[i][j][1];
            const float v2 = acc[i][j][2], v3 = acc[i][j][3];
            if (sel == 3) {
                float2 o1, o2;
                o1.x = v0 + bias[col]; o1.y = v1 + bias[col+1];
                o2.x = v2 + bias[col]; o2.y = v3 + bias[col+1];
                *(float2*)(outF + (size_t)r1 * DD + col) = o1;
                *(float2*)(outF + (size_t)r2 * DD + col) = o2;
            } else {
                *(__half2*)(oH + (size_t)r1 * DD + col) =
                    __floats2half2_rn(v0*f, v1*f);
                *(__half2*)(oH + (size_t)r2 * DD + col) =
                    __floats2half2_rn(v2*f, v3*f);
            }
        }
    }
}

// ---------------- causal flash attention (fp16 mma, f16x2 softmax) ------------
// Round-12 structure exactly: 64-key stages, 3-stage ring, issue after compute.
#define FLD 72
#define ST_ONE  (64*FLD*2)                    /* 9216  */
#define ST_BYTES (2*ST_ONE)                   /* 18432: K + V per stage */
#define FLASH_SMEM (3*ST_BYTES)               /* 55296 */

__global__ __launch_bounds__(256, 2)
void flash_mma(const __half* __restrict__ Qh, const __half* __restrict__ Kh,
               const __half* __restrict__ Vh, __half* __restrict__ Ch)
{
    extern __shared__ char smc[];
    const uint32_t smu = s2u(smc);

    const int t = threadIdx.x;
    const int w = t >> 5, lane = t & 31;
    const int g = lane >> 2, qd = lane & 3;
    const int qd2 = qd * 2;
    const int qb = (gridDim.x - 1) - blockIdx.x;
    const int h = blockIdx.y, b = blockIdx.z;

    const size_t qrow0 = (size_t)b * SS + qb * 128;
    const size_t krow0 = (size_t)b * SS;
    const int hc = h * HDIM;
    const int kbmax = 2*qb + 1;

    const int qa_r = 16*w + (lane & 15);
    const int qa_c = (lane >> 4) * 8;
    const int kb_r = (lane & 7) + ((lane >> 4) << 3);
    const int kb_c = ((lane >> 3) & 1) * 8;
    const int v_r  = (lane & 7) + (((lane >> 3) & 1) << 3);
    const int v_c  = (lane >> 4) * 8;

    // ---- Q staging: 128 rows x 128 B = 1024 chunks of 16B (4 sweeps) ----
#pragma unroll
    for (int i = 0; i < 4; i++) {
        const int idx = t + 256*i;              // 0..1023
        const int row = idx >> 3, col = (idx & 7) * 8;
        cpa16(smu + (uint32_t)(row*FLD + col)*2, Qh + (qrow0 + row)*DD + hc + col);
    }
    cp_commit();
    cp_wait<0>();
    __syncthreads();

    uint32_t qa[4][4];
#pragma unroll
    for (int s = 0; s < 4; s++)
        ldsm4(qa[s], smu + (uint32_t)(qa_r*FLD + s*16 + qa_c)*2);
    __syncthreads();

    auto issue_kv = [&](int kb) {
        const uint32_t sb = smu + (kb % 3)*ST_BYTES;
#pragma unroll
        for (int i = 0; i < 2; i++) {
            const int idx = t + 256*i;
            const int row = idx >> 3, col = (idx & 7) * 8;
            const uint32_t so = (uint32_t)(row*FLD + col) * 2;
            const size_t gr = (krow0 + kb*64 + row)*DD + hc + col;
            cpa16(sb + so,          Kh + gr);
            cpa16(sb + ST_ONE + so, Vh + gr);
        }
        cp_commit();
    };
    issue_kv(0);
    issue_kv(1);

    float sc[8][4], o[8][4];
#pragma unroll
    for (int j = 0; j < 8; j++)
#pragma unroll
        for (int e = 0; e < 4; e++) o[j][e] = 0.f;
    const float NEG_INF = __int_as_float(0xff800000u);
    float m0 = NEG_INF, m1 = NEG_INF, l0 = 0.f, l1 = 0.f;

    const int grow0 = qb*128 + 16*w + g;
    const int grow1 = grow0 + 8;
    const int wrow_max = qb*128 + 16*w + 15;

    const uint32_t ones2 = 0x3C003C00u;       // half2(1, 1)
    const uint32_t onesb[2] = {ones2, ones2};

    for (int kb = 0; kb <= kbmax; kb++) {
        const int st = kb % 3;
        if (kb == kbmax) cp_wait<0>();
        else             cp_wait<1>();
        __syncthreads();

        const bool active = (kb*64 <= wrow_max);
        if (active) {
            const uint32_t skh = smu + st*ST_BYTES;
            const uint32_t svb = skh + ST_ONE;

#pragma unroll
            for (int j = 0; j < 8; j++)
#pragma unroll
                for (int e = 0; e < 4; e++) sc[j][e] = 0.f;

#pragma unroll
            for (int s = 0; s < 4; s++) {
#pragma unroll
                for (int jp = 0; jp < 4; jp++) {
                    uint32_t bh[4];
                    ldsm4(bh, skh +
                          (uint32_t)((jp*16 + kb_r)*FLD + s*16 + kb_c)*2);
                    mma_f16(sc[2*jp  ], qa[s], bh);
                    mma_f16(sc[2*jp+1], qa[s], bh + 2);
                }
            }

            // ---- causal mask + row max (scale pre-folded into Q) ----
            const bool diag = (kb >= 2*qb);
            float mx0 = NEG_INF, mx1 = NEG_INF;
#pragma unroll
            for (int j = 0; j < 8; j++) {
                if (diag) {
                    const int c0 = kb*64 + j*8 + qd2, c1 = c0 + 1;
                    if (c0 > grow0) sc[j][0] = NEG_INF;
                    if (c1 > grow0) sc[j][1] = NEG_INF;
                    if (c0 > grow1) sc[j][2] = NEG_INF;
                    if (c1 > grow1) sc[j][3] = NEG_INF;
                }
                mx0 = fmaxf(mx0, fmaxf(sc[j][0], sc[j][1]));
                mx1 = fmaxf(mx1, fmaxf(sc[j][2], sc[j][3]));
            }
            mx0 = fmaxf(mx0, __shfl_xor_sync(0xffffffffu, mx0, 1));
            mx0 = fmaxf(mx0, __shfl_xor_sync(0xffffffffu, mx0, 2));
            mx1 = fmaxf(mx1, __shfl_xor_sync(0xffffffffu, mx1, 1));
            mx1 = fmaxf(mx1, __shfl_xor_sync(0xffffffffu, mx1, 2));

            const float mn0 = fmaxf(m0, mx0), mn1 = fmaxf(m1, mx1);
            const float al0 = exp2f(m0 - mn0), al1 = exp2f(m1 - mn1);
            m0 = mn0; m1 = mn1;

            // ---- p = exp2(s - m) in packed fp16 (ready PV fragments) ----
            uint32_t pf[8][2];
#pragma unroll
            for (int j = 0; j < 8; j++) {
                pf[j][0] = exp2_f16x2(sc[j][0] - mn0, sc[j][1] - mn0);
                pf[j][1] = exp2_f16x2(sc[j][2] - mn1, sc[j][3] - mn1);
            }

            // ---- rescale o ----
#pragma unroll
            for (int j = 0; j < 8; j++) {
                o[j][0] *= al0; o[j][1] *= al0;
                o[j][2] *= al1; o[j][3] *= al1;
            }

            // ---- PV + row-sum (ones column) ----
            float lacc[4] = {0.f, 0.f, 0.f, 0.f};
#pragma unroll
            for (int s = 0; s < 4; s++) {
                uint32_t a[4];
                a[0] = pf[2*s  ][0]; a[1] = pf[2*s  ][1];
                a[2] = pf[2*s+1][0]; a[3] = pf[2*s+1][1];
                mma_f16(lacc, a, onesb);       // exact fp32 row sums of fp16 P
#pragma unroll
                for (int jp = 0; jp < 4; jp++) {
                    uint32_t bv[4];
                    ldsm4t(bv, svb + (uint32_t)((s*16 + v_r)*FLD + jp*16 + v_c)*2);
                    mma_f16(o[2*jp  ], a, bv);
                    mma_f16(o[2*jp+1], a, bv + 2);
                }
            }
            l0 = l0 * al0 + lacc[0];
            l1 = l1 * al1 + lacc[2];
        }
        if (kb + 2 <= kbmax) issue_kv(kb + 2);   // r12 schedule: after compute
    }

    // ---- epilogue ----
    const float inv0 = 1.f / l0, inv1 = 1.f / l1;
    const size_t r1 = qrow0 + 16*w + g;
    const size_t r2 = r1 + 8;
#pragma unroll
    for (int j = 0; j < 8; j++) {
        const int col = hc + j*8 + qd2;
        *(__half2*)(Ch + r1*DD + col) =
            __floats2half2_rn(o[j][0]*inv0, o[j][1]*inv0);
        *(__half2*)(Ch + r2*DD + col) =
            __floats2half2_rn(o[j][2]*inv1, o[j][3]*inv1);
    }
}

// ---------------------------------------------------------------------------
extern "C" void kernel_launch(void* const* d_in, const int* in_sizes, int n_in,
                              void* d_out, int out_size)
{
    const float* x  = (const float*)d_in[0];
    const float* Wq = (const float*)d_in[1];
    const float* Wk = (const float*)d_in[2];
    const float* Wv = (const float*)d_in[3];
    const float* Wo = (const float*)d_in[4];
    const float* bo = (const float*)d_in[5];
    float* out = (float*)d_out;

    __half *xh, *qh, *kh, *vh, *ch, *wh;
    cudaGetSymbolAddress((void**)&xh, g_xh);
    cudaGetSymbolAddress((void**)&qh, g_qh);
    cudaGetSymbolAddress((void**)&kh, g_kh);
    cudaGetSymbolAddress((void**)&vh, g_vh);
    cudaGetSymbolAddress((void**)&ch, g_ch);
    cudaGetSymbolAddress((void**)&wh, g_wh);

    cudaFuncSetAttribute(gemm_fused,
                         cudaFuncAttributeMaxDynamicSharedMemorySize, GEMM_SMEM);
    cudaFuncSetAttribute(flash_mma,
                         cudaFuncAttributeMaxDynamicSharedMemorySize, FLASH_SMEM);

    // prep: weight transpose + x->fp16, one launch (z=0..3 weights, z=4 x)
    const int n4 = MROWS * DD / 4;
    dim3 pb(32, 8), pg(DD/32, DD/32, 5);
    prep_kernel<<<pg, pb>>>(Wq, Wk, Wv, Wo, wh, (const float4*)x,
                            (__half2*)xh, n4);

    // fused QKV projections
    dim3 gq(3 * DD / 128, MROWS / 128);   // (24, 64)
    gemm_fused<<<gq, 256, GEMM_SMEM>>>(xh, wh, nullptr,
                                       qh, kh, vh, nullptr, 0);

    // attention
    dim3 gf(SS / 128, NH, BB);            // (16, 16, 4)
    flash_mma<<<gf, 256, FLASH_SMEM>>>(qh, kh, vh, ch);

    // output projection + bias
    dim3 go(DD / 128, MROWS / 128);       // (8, 64)
    gemm_fused<<<go, 256, GEMM_SMEM>>>(ch, wh, bo,
                                       nullptr, nullptr, nullptr, out, 3);
}

// round 16
// speedup vs baseline: 1.0879x; 1.0071x over previous
#include <cuda_runtime.h>
#include <cuda_bf16.h>
#include <cuda_fp16.h>
#include <math.h>
#include <stdint.h>

#define BB 4
#define SS 2048
#define DD 1024
#define NH 16
#define HDIM 64
#define MROWS (BB*SS)   /* 8192 */

#define SC_SCALE 0.180336880f   /* 0.125 * log2(e), folded into Q projection */

// ---------------- scratch (__device__ globals; allocs forbidden) ------------
__device__ __half g_xh[MROWS*DD];
__device__ __half g_qh[MROWS*DD];
__device__ __half g_kh[MROWS*DD];
__device__ __half g_vh[MROWS*DD];
__device__ __half g_ch[MROWS*DD];
__device__ __half g_wh[4][DD*DD];   // transposed fp16: [Wq, Wk, Wv, Wo]

// ---------------- ptx helpers -------------------------------------------------
static __device__ __forceinline__ void mma_f16(float* c, const uint32_t* a,
                                               const uint32_t* b) {
    asm volatile(
        "mma.sync.aligned.m16n8k16.row.col.f32.f16.f16.f32 "
        "{%0,%1,%2,%3}, {%4,%5,%6,%7}, {%8,%9}, {%0,%1,%2,%3};"
        : "+f"(c[0]), "+f"(c[1]), "+f"(c[2]), "+f"(c[3])
        : "r"(a[0]), "r"(a[1]), "r"(a[2]), "r"(a[3]), "r"(b[0]), "r"(b[1]));
}
static __device__ __forceinline__ void ldsm4(uint32_t* r, uint32_t a) {
    asm volatile("ldmatrix.sync.aligned.m8n8.x4.shared.b16 {%0,%1,%2,%3}, [%4];"
                 : "=r"(r[0]), "=r"(r[1]), "=r"(r[2]), "=r"(r[3]) : "r"(a));
}
static __device__ __forceinline__ void ldsm4t(uint32_t* r, uint32_t a) {
    asm volatile("ldmatrix.sync.aligned.m8n8.x4.trans.shared.b16 {%0,%1,%2,%3}, [%4];"
                 : "=r"(r[0]), "=r"(r[1]), "=r"(r[2]), "=r"(r[3]) : "r"(a));
}
static __device__ __forceinline__ uint32_t s2u(const void* p) {
    uint32_t a;
    asm("{ .reg .u64 t; cvta.to.shared.u64 t, %1; cvt.u32.u64 %0, t; }"
        : "=r"(a) : "l"(p));
    return a;
}
static __device__ __forceinline__ void cpa16(uint32_t dst, const void* src) {
    asm volatile("cp.async.cg.shared.global [%0], [%1], 16;"
                 :: "r"(dst), "l"(src));
}
static __device__ __forceinline__ void cp_commit() {
    asm volatile("cp.async.commit_group;");
}
template<int N>
static __device__ __forceinline__ void cp_wait() {
    asm volatile("cp.async.wait_group %0;" :: "n"(N));
}
// exp2 of two fp32 values via packed fp16: result is a ready PV A-fragment half2
static __device__ __forceinline__ uint32_t exp2_f16x2(float lo, float hi) {
    uint32_t h, r;
    asm("cvt.rn.f16x2.f32 %0, %1, %2;" : "=r"(h) : "f"(hi), "f"(lo));
    asm("ex2.approx.f16x2 %0, %1;" : "=r"(r) : "r"(h));
    return r;
}

// ---------------- prep kernel: weight transpose (z<4) + x convert (z==4) -----
__global__ void prep_kernel(const float* __restrict__ W0,
                            const float* __restrict__ W1,
                            const float* __restrict__ W2,
                            const float* __restrict__ W3,
                            __half* __restrict__ wh,
                            const float4* __restrict__ x,
                            __half2* __restrict__ xh, int n4)
{
    __shared__ float t[32][33];
    const int z = blockIdx.z;
    const int tx = threadIdx.x, ty = threadIdx.y;   // 32 x 8

    if (z < 4) {
        const float* Ws[4] = {W0, W1, W2, W3};
        const float* W = Ws[z];
        __half* th = wh + (size_t)z * DD * DD;
        const int n0 = blockIdx.x * 32, k0 = blockIdx.y * 32;
#pragma unroll
        for (int i = 0; i < 32; i += 8)
            t[ty + i][tx] = W[(size_t)(k0 + ty + i) * DD + n0 + tx];
        __syncthreads();
#pragma unroll
        for (int i = 0; i < 32; i += 8) {
            size_t o = (size_t)(n0 + ty + i) * DD + k0 + tx;
            th[o] = __float2half_rn(t[tx][ty + i]);
        }
    } else {
        const int tid = (blockIdx.y * gridDim.x + blockIdx.x) * 256 + ty * 32 + tx;
        const int nthreads = gridDim.x * gridDim.y * 256;
        for (int i = tid; i < n4; i += nthreads) {
            float4 v = x[i];
            xh[2*i]   = __floats2half2_rn(v.x, v.y);
            xh[2*i+1] = __floats2half2_rn(v.z, v.w);
        }
    }
}

// ---------------- fused fp16 mma.sync GEMM ------------------------------------
// sel = sel_base + blockIdx.x/8:
//   0: x@Wq*SC_SCALE -> qh   1: x@Wk -> kh   2: x@Wv -> vh
//   3: ctx@Wo+bias -> outF
#define ALD2 72
#define G_MAT2 (128*ALD2)
#define NSTG 16
#define GEMM_SMEM (2 * 3 * G_MAT2 * 2)          /* 110592 bytes */

__global__ __launch_bounds__(256, 2)
void gemm_fused(const __half* __restrict__ A, const __half* __restrict__ wh,
                const float* __restrict__ bias,
                __half* __restrict__ qh, __half* __restrict__ kh,
                __half* __restrict__ vh, float* __restrict__ outF,
                int sel_base)
{
    extern __shared__ char smg[];
    const uint32_t asu = s2u(smg);
    const uint32_t bsu = asu + 3 * G_MAT2 * 2;

    const int t = threadIdx.x;
    const int wid = t >> 5, lane = t & 31;
    const int wm = wid & 1, wn = wid >> 1;
    const int g = lane >> 2, qd = lane & 3;
    const int qd2 = qd * 2;
    const int sel = sel_base + (blockIdx.x >> 3);
    const int n0 = (blockIdx.x & 7) * 128;
    const int m0 = blockIdx.y * 128;

    const __half* B = wh + (size_t)sel * DD * DD;

    const int ld_row = t >> 3;
    const int ld_col = (t & 7) * 8;

    const int a_r = wm*64 + (lane & 15);
    const int a_c = (lane >> 4) * 8;
    const int b_r = wn*32 + (lane & 7) + ((lane >> 4) << 3);
    const int b_c = ((lane >> 3) & 1) * 8;

    float acc[4][4][4];
#pragma unroll
    for (int i = 0; i < 4; i++)
#pragma unroll
        for (int j = 0; j < 4; j++)
#pragma unroll
            for (int e = 0; e < 4; e++) acc[i][j][e] = 0.f;

    auto issue = [&](int s) {
        const int st = s % 3;
        const int kc = s * 64;
#pragma unroll
        for (int i = 0; i < 4; i++) {
            const int row = ld_row + i*32;
            const uint32_t so = (uint32_t)(st*G_MAT2 + row*ALD2 + ld_col) * 2;
            cpa16(asu + so, A + (size_t)(m0 + row) * DD + kc + ld_col);
            cpa16(bsu + so, B + (size_t)(n0 + row) * DD + kc + ld_col);
        }
        cp_commit();
    };

    issue(0);
    issue(1);

    for (int s = 0; s < NSTG; s++) {
        const int st = s % 3;
        if (s == NSTG - 1) cp_wait<0>();
        else               cp_wait<1>();
        __syncthreads();

        const uint32_t ab = asu + (uint32_t)(st*G_MAT2)*2;
        const uint32_t bb = bsu + (uint32_t)(st*G_MAT2)*2;
#pragma unroll
        for (int kk = 0; kk < 4; kk++) {
            uint32_t a[4][4], b4[2][4];
#pragma unroll
            for (int i = 0; i < 4; i++)
                ldsm4(a[i], ab + (uint32_t)((a_r + i*16)*ALD2 + kk*16 + a_c)*2);
#pragma unroll
            for (int jp = 0; jp < 2; jp++)
                ldsm4(b4[jp], bb + (uint32_t)((b_r + jp*16)*ALD2 + kk*16 + b_c)*2);
#pragma unroll
            for (int i = 0; i < 4; i++)
#pragma unroll
                for (int j = 0; j < 4; j++)
                    mma_f16(acc[i][j], a[i], &b4[j >> 1][(j & 1) * 2]);
        }
        if (s + 2 < NSTG) issue(s + 2);   // issue AFTER compute (r12 schedule)
    }

    // epilogue
    __half* oH = (sel == 0) ? qh : ((sel == 1) ? kh : vh);
    const float f = (sel == 0) ? SC_SCALE : 1.0f;
#pragma unroll
    for (int i = 0; i < 4; i++) {
        const int r1 = m0 + wm*64 + i*16 + g;
        const int r2 = r1 + 8;
#pragma unroll
        for (int j = 0; j < 4; j++) {
            const int col = n0 + wn*32 + j*8 + qd2;
            const float v0 = acc[i][j][0], v1 = acc[i][j][1];
            const float v2 = acc[i][j][2], v3 = acc[i][j][3];
            if (sel == 3) {
                float2 o1, o2;
                o1.x = v0 + bias[col]; o1.y = v1 + bias[col+1];
                o2.x = v2 + bias[col]; o2.y = v3 + bias[col+1];
                *(float2*)(outF + (size_t)r1 * DD + col) = o1;
                *(float2*)(outF + (size_t)r2 * DD + col) = o2;
            } else {
                *(__half2*)(oH + (size_t)r1 * DD + col) =
                    __floats2half2_rn(v0*f, v1*f);
                *(__half2*)(oH + (size_t)r2 * DD + col) =
                    __floats2half2_rn(v2*f, v3*f);
            }
        }
    }
}

// ---------------- causal flash attention (fp16 mma, 128-key stages) -----------
// r12 numerics/inner loops exactly; stage = 128 keys (two 64-key halves),
// 3-stage ring -> barriers halved. NO per-block predication (r13 lesson);
// only tile-level break. cp.async issued AFTER compute (r14 lesson).
#define FLD 72
#define ST_HALF (64*FLD*2)                    /* 9216  */
#define ST_MAT  (2*ST_HALF)                   /* 18432: 128-key K or V tile */
#define ST_BYTES (2*ST_MAT)                   /* 36864: K+V per stage */
#define FLASH_SMEM (3*ST_BYTES)               /* 110592 */

__global__ __launch_bounds__(256, 2)
void flash_mma(const __half* __restrict__ Qh, const __half* __restrict__ Kh,
               const __half* __restrict__ Vh, __half* __restrict__ Ch)
{
    extern __shared__ char smc[];
    const uint32_t smu = s2u(smc);

    const int t = threadIdx.x;
    const int w = t >> 5, lane = t & 31;
    const int g = lane >> 2, qd = lane & 3;
    const int qd2 = qd * 2;
    const int qb = (gridDim.x - 1) - blockIdx.x;   // heavy tiles first
    const int h = blockIdx.y, b = blockIdx.z;

    const size_t qrow0 = (size_t)b * SS + qb * 128;
    const size_t krow0 = (size_t)b * SS;
    const int hc = h * HDIM;
    const int smax = qb;                     // 128-key stages: 0..qb

    const int qa_r = 16*w + (lane & 15);
    const int qa_c = (lane >> 4) * 8;
    const int kb_r = (lane & 7) + ((lane >> 4) << 3);
    const int kb_c = ((lane >> 3) & 1) * 8;
    const int v_r  = (lane & 7) + (((lane >> 3) & 1) << 3);
    const int v_c  = (lane >> 4) * 8;

    // ---- Q staging: 128 rows x 128 B = 1024 chunks of 16B (4 sweeps) ----
#pragma unroll
    for (int i = 0; i < 4; i++) {
        const int idx = t + 256*i;              // 0..1023
        const int row = idx >> 3, col = (idx & 7) * 8;
        cpa16(smu + (uint32_t)(row*FLD + col)*2, Qh + (qrow0 + row)*DD + hc + col);
    }
    cp_commit();
    cp_wait<0>();
    __syncthreads();

    uint32_t qa[4][4];
#pragma unroll
    for (int s = 0; s < 4; s++)
        ldsm4(qa[s], smu + (uint32_t)(qa_r*FLD + s*16 + qa_c)*2);
    __syncthreads();                    // Q region about to be reused by ring

    auto issue_kv = [&](int s) {
        const uint32_t sb = smu + (s % 3)*ST_BYTES;
#pragma unroll
        for (int i = 0; i < 4; i++) {
            const int idx = t + 256*i;          // 0..1023 -> 128 rows
            const int row = idx >> 3, col = (idx & 7) * 8;
            const uint32_t so = (uint32_t)(row*FLD + col) * 2;
            const size_t gr = (krow0 + (size_t)s*128 + row)*DD + hc + col;
            cpa16(sb + so,          Kh + gr);
            cpa16(sb + ST_MAT + so, Vh + gr);
        }
        cp_commit();
    };
    issue_kv(0);
    if (smax >= 1) issue_kv(1);

    float sc[8][4], o[8][4];
#pragma unroll
    for (int j = 0; j < 8; j++)
#pragma unroll
        for (int e = 0; e < 4; e++) o[j][e] = 0.f;
    const float NEG_INF = __int_as_float(0xff800000u);
    float m0 = NEG_INF, m1 = NEG_INF, l0 = 0.f, l1 = 0.f;

    const int grow0 = qb*128 + 16*w + g;
    const int grow1 = grow0 + 8;
    const int wrow_max = qb*128 + 16*w + 15;

    const uint32_t ones2 = 0x3C003C00u;       // half2(1, 1)
    const uint32_t onesb[2] = {ones2, ones2};

    for (int s = 0; s <= smax; s++) {
        if (s == smax) cp_wait<0>();
        else           cp_wait<1>();
        __syncthreads();

        const uint32_t stg = smu + (s % 3)*ST_BYTES;
#pragma unroll
        for (int h2 = 0; h2 < 2; h2++) {
            const int kb = 2*s + h2;
            if (kb*64 > wrow_max) break;       // fully-masked: tile-level skip
            const uint32_t skh = stg + h2*ST_HALF;
            const uint32_t svb = stg + ST_MAT + h2*ST_HALF;

#pragma unroll
            for (int j = 0; j < 8; j++)
#pragma unroll
                for (int e = 0; e < 4; e++) sc[j][e] = 0.f;

#pragma unroll
            for (int ss = 0; ss < 4; ss++) {
#pragma unroll
                for (int jp = 0; jp < 4; jp++) {
                    uint32_t bh[4];
                    ldsm4(bh, skh +
                          (uint32_t)((jp*16 + kb_r)*FLD + ss*16 + kb_c)*2);
                    mma_f16(sc[2*jp  ], qa[ss], bh);
                    mma_f16(sc[2*jp+1], qa[ss], bh + 2);
                }
            }

            // ---- causal mask + row max (scale pre-folded into Q) ----
            const bool diag = (kb >= 2*qb);
            float mx0 = NEG_INF, mx1 = NEG_INF;
#pragma unroll
            for (int j = 0; j < 8; j++) {
                if (diag) {
                    const int c0 = kb*64 + j*8 + qd2, c1 = c0 + 1;
                    if (c0 > grow0) sc[j][0] = NEG_INF;
                    if (c1 > grow0) sc[j][1] = NEG_INF;
                    if (c0 > grow1) sc[j][2] = NEG_INF;
                    if (c1 > grow1) sc[j][3] = NEG_INF;
                }
                mx0 = fmaxf(mx0, fmaxf(sc[j][0], sc[j][1]));
                mx1 = fmaxf(mx1, fmaxf(sc[j][2], sc[j][3]));
            }
            mx0 = fmaxf(mx0, __shfl_xor_sync(0xffffffffu, mx0, 1));
            mx0 = fmaxf(mx0, __shfl_xor_sync(0xffffffffu, mx0, 2));
            mx1 = fmaxf(mx1, __shfl_xor_sync(0xffffffffu, mx1, 1));
            mx1 = fmaxf(mx1, __shfl_xor_sync(0xffffffffu, mx1, 2));

            const float mn0 = fmaxf(m0, mx0), mn1 = fmaxf(m1, mx1);
            const float al0 = exp2f(m0 - mn0), al1 = exp2f(m1 - mn1);
            m0 = mn0; m1 = mn1;

            // ---- p = exp2(s - m) in packed fp16 (ready PV fragments) ----
            uint32_t pf[8][2];
#pragma unroll
            for (int j = 0; j < 8; j++) {
                pf[j][0] = exp2_f16x2(sc[j][0] - mn0, sc[j][1] - mn0);
                pf[j][1] = exp2_f16x2(sc[j][2] - mn1, sc[j][3] - mn1);
            }

            // ---- rescale o ----
#pragma unroll
            for (int j = 0; j < 8; j++) {
                o[j][0] *= al0; o[j][1] *= al0;
                o[j][2] *= al1; o[j][3] *= al1;
            }

            // ---- PV + row-sum (ones column) ----
            float lacc[4] = {0.f, 0.f, 0.f, 0.f};
#pragma unroll
            for (int ss = 0; ss < 4; ss++) {
                uint32_t a[4];
                a[0] = pf[2*ss  ][0]; a[1] = pf[2*ss  ][1];
                a[2] = pf[2*ss+1][0]; a[3] = pf[2*ss+1][1];
                mma_f16(lacc, a, onesb);
#pragma unroll
                for (int jp = 0; jp < 4; jp++) {
                    uint32_t bv[4];
                    ldsm4t(bv, svb +
                           (uint32_t)((ss*16 + v_r)*FLD + jp*16 + v_c)*2);
                    mma_f16(o[2*jp  ], a, bv);
                    mma_f16(o[2*jp+1], a, bv + 2);
                }
            }
            l0 = l0 * al0 + lacc[0];
            l1 = l1 * al1 + lacc[2];
        }
        if (s + 2 <= smax) issue_kv(s + 2);   // AFTER compute (r14 lesson)
    }

    // ---- epilogue ----
    const float inv0 = 1.f / l0, inv1 = 1.f / l1;
    const size_t r1 = qrow0 + 16*w + g;
    const size_t r2 = r1 + 8;
#pragma unroll
    for (int j = 0; j < 8; j++) {
        const int col = hc + j*8 + qd2;
        *(__half2*)(Ch + r1*DD + col) =
            __floats2half2_rn(o[j][0]*inv0, o[j][1]*inv0);
        *(__half2*)(Ch + r2*DD + col) =
            __floats2half2_rn(o[j][2]*inv1, o[j][3]*inv1);
    }
}

// ---------------------------------------------------------------------------
extern "C" void kernel_launch(void* const* d_in, const int* in_sizes, int n_in,
                              void* d_out, int out_size)
{
    const float* x  = (const float*)d_in[0];
    const float* Wq = (const float*)d_in[1];
    const float* Wk = (const float*)d_in[2];
    const float* Wv = (const float*)d_in[3];
    const float* Wo = (const float*)d_in[4];
    const float* bo = (const float*)d_in[5];
    float* out = (float*)d_out;

    __half *xh, *qh, *kh, *vh, *ch, *wh;
    cudaGetSymbolAddress((void**)&xh, g_xh);
    cudaGetSymbolAddress((void**)&qh, g_qh);
    cudaGetSymbolAddress((void**)&kh, g_kh);
    cudaGetSymbolAddress((void**)&vh, g_vh);
    cudaGetSymbolAddress((void**)&ch, g_ch);
    cudaGetSymbolAddress((void**)&wh, g_wh);

    cudaFuncSetAttribute(gemm_fused,
                         cudaFuncAttributeMaxDynamicSharedMemorySize, GEMM_SMEM);
    cudaFuncSetAttribute(flash_mma,
                         cudaFuncAttributeMaxDynamicSharedMemorySize, FLASH_SMEM);

    // prep: weight transpose + x->fp16, one launch
    const int n4 = MROWS * DD / 4;
    dim3 pb(32, 8), pg(DD/32, DD/32, 5);
    prep_kernel<<<pg, pb>>>(Wq, Wk, Wv, Wo, wh, (const float4*)x,
                            (__half2*)xh, n4);

    // fused QKV projections
    dim3 gq(3 * DD / 128, MROWS / 128);   // (24, 64)
    gemm_fused<<<gq, 256, GEMM_SMEM>>>(xh, wh, nullptr,
                                       qh, kh, vh, nullptr, 0);

    // attention
    dim3 gf(SS / 128, NH, BB);            // (16, 16, 4)
    flash_mma<<<gf, 256, FLASH_SMEM>>>(qh, kh, vh, ch);

    // output projection + bias
    dim3 go(DD / 128, MROWS / 128);       // (8, 64)
    gemm_fused<<<go, 256, GEMM_SMEM>>>(ch, wh, bo,
                                       nullptr, nullptr, nullptr, out, 3);
}

// round 17
// speedup vs baseline: 1.0996x; 1.0107x over previous
#include <cuda_runtime.h>
#include <cuda_bf16.h>
#include <cuda_fp16.h>
#include <math.h>
#include <stdint.h>

#define BB 4
#define SS 2048
#define DD 1024
#define NH 16
#define HDIM 64
#define MROWS (BB*SS)   /* 8192 */

#define SC_SCALE 0.180336880f   /* 0.125 * log2(e), folded into Q projection */

// ---------------- scratch (__device__ globals; allocs forbidden) ------------
__device__ __half g_xh[MROWS*DD];
__device__ __half g_qh[MROWS*DD];
__device__ __half g_kh[MROWS*DD];
__device__ __half g_vh[MROWS*DD];
__device__ __half g_ch[MROWS*DD];
__device__ __half g_wh[4][DD*DD];   // fp16 weights, UNtransposed: W[k][n]

// ---------------- ptx helpers -------------------------------------------------
static __device__ __forceinline__ void mma_f16(float* c, const uint32_t* a,
                                               const uint32_t* b) {
    asm volatile(
        "mma.sync.aligned.m16n8k16.row.col.f32.f16.f16.f32 "
        "{%0,%1,%2,%3}, {%4,%5,%6,%7}, {%8,%9}, {%0,%1,%2,%3};"
        : "+f"(c[0]), "+f"(c[1]), "+f"(c[2]), "+f"(c[3])
        : "r"(a[0]), "r"(a[1]), "r"(a[2]), "r"(a[3]), "r"(b[0]), "r"(b[1]));
}
static __device__ __forceinline__ void ldsm4(uint32_t* r, uint32_t a) {
    asm volatile("ldmatrix.sync.aligned.m8n8.x4.shared.b16 {%0,%1,%2,%3}, [%4];"
                 : "=r"(r[0]), "=r"(r[1]), "=r"(r[2]), "=r"(r[3]) : "r"(a));
}
static __device__ __forceinline__ void ldsm4t(uint32_t* r, uint32_t a) {
    asm volatile("ldmatrix.sync.aligned.m8n8.x4.trans.shared.b16 {%0,%1,%2,%3}, [%4];"
                 : "=r"(r[0]), "=r"(r[1]), "=r"(r[2]), "=r"(r[3]) : "r"(a));
}
static __device__ __forceinline__ uint32_t s2u(const void* p) {
    uint32_t a;
    asm("{ .reg .u64 t; cvta.to.shared.u64 t, %1; cvt.u32.u64 %0, t; }"
        : "=r"(a) : "l"(p));
    return a;
}
static __device__ __forceinline__ void cpa16(uint32_t dst, const void* src) {
    asm volatile("cp.async.cg.shared.global [%0], [%1], 16;"
                 :: "r"(dst), "l"(src));
}
static __device__ __forceinline__ void cp_commit() {
    asm volatile("cp.async.commit_group;");
}
template<int N>
static __device__ __forceinline__ void cp_wait() {
    asm volatile("cp.async.wait_group %0;" :: "n"(N));
}
// exp2 of two fp32 values via packed fp16: result is a ready PV A-fragment half2
static __device__ __forceinline__ uint32_t exp2_f16x2(float lo, float hi) {
    uint32_t h, r;
    asm("cvt.rn.f16x2.f32 %0, %1, %2;" : "=r"(h) : "f"(hi), "f"(lo));
    asm("ex2.approx.f16x2 %0, %1;" : "=r"(r) : "r"(h));
    return r;
}

// ---------------- prep: pure streaming fp32 -> fp16 convert -------------------
// z = 0..3: W0..W3 -> wh[z] (NO transpose); z = 4: x -> xh (grid-stride).
__global__ void prep_kernel(const float* __restrict__ W0,
                            const float* __restrict__ W1,
                            const float* __restrict__ W2,
                            const float* __restrict__ W3,
                            __half* __restrict__ wh,
                            const float4* __restrict__ x,
                            __half2* __restrict__ xh, int n4x)
{
    const int z = blockIdx.z;
    const int tid = blockIdx.x * 256 + threadIdx.x;
    const int nthreads = gridDim.x * 256;

    if (z < 4) {
        const float* Ws[4] = {W0, W1, W2, W3};
        const float4* src = (const float4*)Ws[z];
        __half2* dst = (__half2*)(wh + (size_t)z * DD * DD);
        const int n4 = DD * DD / 4;
        for (int i = tid; i < n4; i += nthreads) {
            float4 v = src[i];
            dst[2*i]   = __floats2half2_rn(v.x, v.y);
            dst[2*i+1] = __floats2half2_rn(v.z, v.w);
        }
    } else {
        for (int i = tid; i < n4x; i += nthreads) {
            float4 v = x[i];
            xh[2*i]   = __floats2half2_rn(v.x, v.y);
            xh[2*i+1] = __floats2half2_rn(v.z, v.w);
        }
    }
}

// ---------------- fused fp16 mma.sync GEMM ------------------------------------
// sel = sel_base + blockIdx.x/8:
//   0: x@Wq*SC_SCALE -> qh   1: x@Wk -> kh   2: x@Wv -> vh
//   3: ctx@Wo+bias -> outF
// A in smem [m][k] (ALD 72, ldsm); B (weight) in smem [k][n] (BLD 136, ldsm4t).
#define ALD2 72
#define BLD2 136
#define A_ST (128*ALD2*2)            /* 18432 bytes */
#define B_ST (64*BLD2*2)             /* 17408 bytes */
#define STG  (A_ST + B_ST)           /* 35840 bytes */
#define NSTG 16
#define GEMM_SMEM (3 * STG)          /* 107520 bytes */

__global__ __launch_bounds__(256, 2)
void gemm_fused(const __half* __restrict__ A, const __half* __restrict__ wh,
                const float* __restrict__ bias,
                __half* __restrict__ qh, __half* __restrict__ kh,
                __half* __restrict__ vh, float* __restrict__ outF,
                int sel_base)
{
    extern __shared__ char smg[];
    const uint32_t smu = s2u(smg);

    const int t = threadIdx.x;
    const int wid = t >> 5, lane = t & 31;
    const int wm = wid & 1, wn = wid >> 1;
    const int g = lane >> 2, qd = lane & 3;
    const int qd2 = qd * 2;
    const int sel = sel_base + (blockIdx.x >> 3);
    const int n0 = (blockIdx.x & 7) * 128;
    const int m0 = blockIdx.y * 128;

    const __half* B = wh + (size_t)sel * DD * DD;   // W[k][n]

    // cp.async mappings
    const int a_row = t >> 3;            // 0..31 (+32 per sweep, 4 sweeps)
    const int a_col = (t & 7) * 8;
    const int b_row = t >> 4;            // 0..15 (+16 per sweep, 4 sweeps)
    const int b_col = (t & 15) * 8;

    // ldsm lane offsets
    const int a_r = wm*64 + (lane & 15);
    const int a_c = (lane >> 4) * 8;
    // trans-ldsm lane offsets for B (same pattern as flash V)
    const int bt_r = (lane & 7) + (((lane >> 3) & 1) << 3);  // k 0..15
    const int bt_c = (lane >> 4) * 8;                        // n {0,8}

    float acc[4][4][4];
#pragma unroll
    for (int i = 0; i < 4; i++)
#pragma unroll
        for (int j = 0; j < 4; j++)
#pragma unroll
            for (int e = 0; e < 4; e++) acc[i][j][e] = 0.f;

    auto issue = [&](int s) {
        const uint32_t sb = smu + (s % 3) * STG;
        const int kc = s * 64;
#pragma unroll
        for (int i = 0; i < 4; i++) {
            const int row = a_row + i*32;
            cpa16(sb + (uint32_t)(row*ALD2 + a_col)*2,
                  A + (size_t)(m0 + row) * DD + kc + a_col);
        }
#pragma unroll
        for (int i = 0; i < 4; i++) {
            const int krow = b_row + i*16;
            cpa16(sb + A_ST + (uint32_t)(krow*BLD2 + b_col)*2,
                  B + (size_t)(kc + krow) * DD + n0 + b_col);
        }
        cp_commit();
    };

    issue(0);
    issue(1);

    for (int s = 0; s < NSTG; s++) {
        if (s == NSTG - 1) cp_wait<0>();
        else               cp_wait<1>();
        __syncthreads();

        const uint32_t ab = smu + (s % 3) * STG;
        const uint32_t bb = ab + A_ST;
#pragma unroll
        for (int kk = 0; kk < 4; kk++) {
            uint32_t a[4][4], b4[2][4];
#pragma unroll
            for (int i = 0; i < 4; i++)
                ldsm4(a[i], ab + (uint32_t)((a_r + i*16)*ALD2 + kk*16 + a_c)*2);
#pragma unroll
            for (int jp = 0; jp < 2; jp++)
                ldsm4t(b4[jp], bb + (uint32_t)((kk*16 + bt_r)*BLD2 +
                                               wn*32 + jp*16 + bt_c)*2);
#pragma unroll
            for (int i = 0; i < 4; i++)
#pragma unroll
                for (int j = 0; j < 4; j++)
                    mma_f16(acc[i][j], a[i], &b4[j >> 1][(j & 1) * 2]);
        }
        if (s + 2 < NSTG) issue(s + 2);   // issue AFTER compute (r12 schedule)
    }

    // epilogue
    __half* oH = (sel == 0) ? qh : ((sel == 1) ? kh : vh);
    const float f = (sel == 0) ? SC_SCALE : 1.0f;
#pragma unroll
    for (int i = 0; i < 4; i++) {
        const int r1 = m0 + wm*64 + i*16 + g;
        const int r2 = r1 + 8;
#pragma unroll
        for (int j = 0; j < 4; j++) {
            const int col = n0 + wn*32 + j*8 + qd2;
            const float v0 = acc[i][j][0], v1 = acc[i][j][1];
            const float v2 = acc[i][j][2], v3 = acc[i][j][3];
            if (sel == 3) {
                float2 o1, o2;
                o1.x = v0 + bias[col]; o1.y = v1 + bias[col+1];
                o2.x = v2 + bias[col]; o2.y = v3 + bias[col+1];
                *(float2*)(outF + (size_t)r1 * DD + col) = o1;
                *(float2*)(outF + (size_t)r2 * DD + col) = o2;
            } else {
                *(__half2*)(oH + (size_t)r1 * DD + col) =
                    __floats2half2_rn(v0*f, v1*f);
                *(__half2*)(oH + (size_t)r2 * DD + col) =
                    __floats2half2_rn(v2*f, v3*f);
            }
        }
    }
}

// ---------------- causal flash attention (fp16 mma, 128-key stages) -----------
// r16 version verbatim (current best): 128-key stages, 3-stage ring,
// tile-level break only, issue after compute.
#define FLD 72
#define ST_HALF (64*FLD*2)                    /* 9216  */
#define ST_MAT  (2*ST_HALF)                   /* 18432 */
#define ST_BYTES (2*ST_MAT)                   /* 36864 */
#define FLASH_SMEM (3*ST_BYTES)               /* 110592 */

__global__ __launch_bounds__(256, 2)
void flash_mma(const __half* __restrict__ Qh, const __half* __restrict__ Kh,
               const __half* __restrict__ Vh, __half* __restrict__ Ch)
{
    extern __shared__ char smc[];
    const uint32_t smu = s2u(smc);

    const int t = threadIdx.x;
    const int w = t >> 5, lane = t & 31;
    const int g = lane >> 2, qd = lane & 3;
    const int qd2 = qd * 2;
    const int qb = (gridDim.x - 1) - blockIdx.x;
    const int h = blockIdx.y, b = blockIdx.z;

    const size_t qrow0 = (size_t)b * SS + qb * 128;
    const size_t krow0 = (size_t)b * SS;
    const int hc = h * HDIM;
    const int smax = qb;

    const int qa_r = 16*w + (lane & 15);
    const int qa_c = (lane >> 4) * 8;
    const int kb_r = (lane & 7) + ((lane >> 4) << 3);
    const int kb_c = ((lane >> 3) & 1) * 8;
    const int v_r  = (lane & 7) + (((lane >> 3) & 1) << 3);
    const int v_c  = (lane >> 4) * 8;

#pragma unroll
    for (int i = 0; i < 4; i++) {
        const int idx = t + 256*i;
        const int row = idx >> 3, col = (idx & 7) * 8;
        cpa16(smu + (uint32_t)(row*FLD + col)*2, Qh + (qrow0 + row)*DD + hc + col);
    }
    cp_commit();
    cp_wait<0>();
    __syncthreads();

    uint32_t qa[4][4];
#pragma unroll
    for (int s = 0; s < 4; s++)
        ldsm4(qa[s], smu + (uint32_t)(qa_r*FLD + s*16 + qa_c)*2);
    __syncthreads();

    auto issue_kv = [&](int s) {
        const uint32_t sb = smu + (s % 3)*ST_BYTES;
#pragma unroll
        for (int i = 0; i < 4; i++) {
            const int idx = t + 256*i;
            const int row = idx >> 3, col = (idx & 7) * 8;
            const uint32_t so = (uint32_t)(row*FLD + col) * 2;
            const size_t gr = (krow0 + (size_t)s*128 + row)*DD + hc + col;
            cpa16(sb + so,          Kh + gr);
            cpa16(sb + ST_MAT + so, Vh + gr);
        }
        cp_commit();
    };
    issue_kv(0);
    if (smax >= 1) issue_kv(1);

    float sc[8][4], o[8][4];
#pragma unroll
    for (int j = 0; j < 8; j++)
#pragma unroll
        for (int e = 0; e < 4; e++) o[j][e] = 0.f;
    const float NEG_INF = __int_as_float(0xff800000u);
    float m0 = NEG_INF, m1 = NEG_INF, l0 = 0.f, l1 = 0.f;

    const int grow0 = qb*128 + 16*w + g;
    const int grow1 = grow0 + 8;
    const int wrow_max = qb*128 + 16*w + 15;

    const uint32_t ones2 = 0x3C003C00u;
    const uint32_t onesb[2] = {ones2, ones2};

    for (int s = 0; s <= smax; s++) {
        if (s == smax) cp_wait<0>();
        else           cp_wait<1>();
        __syncthreads();

        const uint32_t stg = smu + (s % 3)*ST_BYTES;
#pragma unroll
        for (int h2 = 0; h2 < 2; h2++) {
            const int kb = 2*s + h2;
            if (kb*64 > wrow_max) break;
            const uint32_t skh = stg + h2*ST_HALF;
            const uint32_t svb = stg + ST_MAT + h2*ST_HALF;

#pragma unroll
            for (int j = 0; j < 8; j++)
#pragma unroll
                for (int e = 0; e < 4; e++) sc[j][e] = 0.f;

#pragma unroll
            for (int ss = 0; ss < 4; ss++) {
#pragma unroll
                for (int jp = 0; jp < 4; jp++) {
                    uint32_t bh[4];
                    ldsm4(bh, skh +
                          (uint32_t)((jp*16 + kb_r)*FLD + ss*16 + kb_c)*2);
                    mma_f16(sc[2*jp  ], qa[ss], bh);
                    mma_f16(sc[2*jp+1], qa[ss], bh + 2);
                }
            }

            const bool diag = (kb >= 2*qb);
            float mx0 = NEG_INF, mx1 = NEG_INF;
#pragma unroll
            for (int j = 0; j < 8; j++) {
                if (diag) {
                    const int c0 = kb*64 + j*8 + qd2, c1 = c0 + 1;
                    if (c0 > grow0) sc[j][0] = NEG_INF;
                    if (c1 > grow0) sc[j][1] = NEG_INF;
                    if (c0 > grow1) sc[j][2] = NEG_INF;
                    if (c1 > grow1) sc[j][3] = NEG_INF;
                }
                mx0 = fmaxf(mx0, fmaxf(sc[j][0], sc[j][1]));
                mx1 = fmaxf(mx1, fmaxf(sc[j][2], sc[j][3]));
            }
            mx0 = fmaxf(mx0, __shfl_xor_sync(0xffffffffu, mx0, 1));
            mx0 = fmaxf(mx0, __shfl_xor_sync(0xffffffffu, mx0, 2));
            mx1 = fmaxf(mx1, __shfl_xor_sync(0xffffffffu, mx1, 1));
            mx1 = fmaxf(mx1, __shfl_xor_sync(0xffffffffu, mx1, 2));

            const float mn0 = fmaxf(m0, mx0), mn1 = fmaxf(m1, mx1);
            const float al0 = exp2f(m0 - mn0), al1 = exp2f(m1 - mn1);
            m0 = mn0; m1 = mn1;

            uint32_t pf[8][2];
#pragma unroll
            for (int j = 0; j < 8; j++) {
                pf[j][0] = exp2_f16x2(sc[j][0] - mn0, sc[j][1] - mn0);
                pf[j][1] = exp2_f16x2(sc[j][2] - mn1, sc[j][3] - mn1);
            }

#pragma unroll
            for (int j = 0; j < 8; j++) {
                o[j][0] *= al0; o[j][1] *= al0;
                o[j][2] *= al1; o[j][3] *= al1;
            }

            float lacc[4] = {0.f, 0.f, 0.f, 0.f};
#pragma unroll
            for (int ss = 0; ss < 4; ss++) {
                uint32_t a[4];
                a[0] = pf[2*ss  ][0]; a[1] = pf[2*ss  ][1];
                a[2] = pf[2*ss+1][0]; a[3] = pf[2*ss+1][1];
                mma_f16(lacc, a, onesb);
#pragma unroll
                for (int jp = 0; jp < 4; jp++) {
                    uint32_t bv[4];
                    ldsm4t(bv, svb +
                           (uint32_t)((ss*16 + v_r)*FLD + jp*16 + v_c)*2);
                    mma_f16(o[2*jp  ], a, bv);
                    mma_f16(o[2*jp+1], a, bv + 2);
                }
            }
            l0 = l0 * al0 + lacc[0];
            l1 = l1 * al1 + lacc[2];
        }
        if (s + 2 <= smax) issue_kv(s + 2);
    }

    const float inv0 = 1.f / l0, inv1 = 1.f / l1;
    const size_t r1 = qrow0 + 16*w + g;
    const size_t r2 = r1 + 8;
#pragma unroll
    for (int j = 0; j < 8; j++) {
        const int col = hc + j*8 + qd2;
        *(__half2*)(Ch + r1*DD + col) =
            __floats2half2_rn(o[j][0]*inv0, o[j][1]*inv0);
        *(__half2*)(Ch + r2*DD + col) =
            __floats2half2_rn(o[j][2]*inv1, o[j][3]*inv1);
    }
}

// ---------------------------------------------------------------------------
extern "C" void kernel_launch(void* const* d_in, const int* in_sizes, int n_in,
                              void* d_out, int out_size)
{
    const float* x  = (const float*)d_in[0];
    const float* Wq = (const float*)d_in[1];
    const float* Wk = (const float*)d_in[2];
    const float* Wv = (const float*)d_in[3];
    const float* Wo = (const float*)d_in[4];
    const float* bo = (const float*)d_in[5];
    float* out = (float*)d_out;

    __half *xh, *qh, *kh, *vh, *ch, *wh;
    cudaGetSymbolAddress((void**)&xh, g_xh);
    cudaGetSymbolAddress((void**)&qh, g_qh);
    cudaGetSymbolAddress((void**)&kh, g_kh);
    cudaGetSymbolAddress((void**)&vh, g_vh);
    cudaGetSymbolAddress((void**)&ch, g_ch);
    cudaGetSymbolAddress((void**)&wh, g_wh);

    cudaFuncSetAttribute(gemm_fused,
                         cudaFuncAttributeMaxDynamicSharedMemorySize, GEMM_SMEM);
    cudaFuncSetAttribute(flash_mma,
                         cudaFuncAttributeMaxDynamicSharedMemorySize, FLASH_SMEM);

    // prep: pure streaming converts (weights untransposed + x), one launch
    const int n4x = MROWS * DD / 4;
    dim3 pg(512, 1, 5);
    prep_kernel<<<pg, 256>>>(Wq, Wk, Wv, Wo, wh, (const float4*)x,
                             (__half2*)xh, n4x);

    // fused QKV projections
    dim3 gq(3 * DD / 128, MROWS / 128);   // (24, 64)
    gemm_fused<<<gq, 256, GEMM_SMEM>>>(xh, wh, nullptr,
                                       qh, kh, vh, nullptr, 0);

    // attention
    dim3 gf(SS / 128, NH, BB);            // (16, 16, 4)
    flash_mma<<<gf, 256, FLASH_SMEM>>>(qh, kh, vh, ch);

    // output projection + bias
    dim3 go(DD / 128, MROWS / 128);       // (8, 64)
    gemm_fused<<<go, 256, GEMM_SMEM>>>(ch, wh, bo,
                                       nullptr, nullptr, nullptr, out, 3);
}